// round 9
// baseline (speedup 1.0000x reference)
#include <cuda_runtime.h>
#include <cuda_bf16.h>
#include <cstdint>

#define NNODES 50000
#define NEDGES 800000
#define HID    128

// ---------------- scratch (device globals; no allocation allowed) ----------
__device__ float g_x[NNODES * HID];
__device__ float g_A[NNODES * HID];
__device__ float g_B[NNODES * HID];
__device__ float g_S[NNODES * HID];
__device__ float g_inv[NNODES];
__device__ float g_mask[NNODES];
__device__ float g_colsum[HID];
__device__ int   g_is64;
// CSR by dst
__device__ int   g_cnt[NNODES];
__device__ int   g_off[NNODES + 1];
__device__ int   g_cur[NNODES];
__device__ int   g_bsum[64];
__device__ int   g_srcs[NEDGES];
__device__ float g_eas[NEDGES];
// 18 weight slices (3 layers x {W1a,W1b,W2,U1a,U1b,U2}), each 128x128 bf16,
// transposed ([out][k], packed row-major), hi and lo parts.
__device__ __nv_bfloat16 g_Wh[18 * 16384];
__device__ __nv_bfloat16 g_Wl[18 * 16384];
// V = W2 @ U1b per layer (hi/lo images) and vb = b2 @ U1b
__device__ __nv_bfloat16 g_Vh[3 * 16384];
__device__ __nv_bfloat16 g_Vl[3 * 16384];
__device__ float g_vb[3 * 128];

// ---------------- helpers ----------------------------------------------------
__device__ __forceinline__ uint32_t smem_to_u32(const void* smem_ptr) {
    uint32_t addr;
    asm("{ .reg .u64 tmp; cvta.to.shared.u64 tmp, %1; cvt.u32.u64 %0, tmp; }"
        : "=r"(addr) : "l"(smem_ptr));
    return addr;
}
__device__ __forceinline__ uint32_t split_pair(float a, float b, uint32_t& lo) {
    __nv_bfloat16 ha = __float2bfloat16(a), hb = __float2bfloat16(b);
    __nv_bfloat16 la = __float2bfloat16(a - __bfloat162float(ha));
    __nv_bfloat16 lb = __float2bfloat16(b - __bfloat162float(hb));
    lo = (uint32_t)__bfloat16_as_ushort(la) | ((uint32_t)__bfloat16_as_ushort(lb) << 16);
    return (uint32_t)__bfloat16_as_ushort(ha) | ((uint32_t)__bfloat16_as_ushort(hb) << 16);
}
__device__ __forceinline__ void ldmatrix_x4(uint32_t& r0, uint32_t& r1,
                                            uint32_t& r2, uint32_t& r3, uint32_t addr) {
    asm volatile("ldmatrix.sync.aligned.m8n8.x4.shared.b16 {%0,%1,%2,%3}, [%4];"
                 : "=r"(r0), "=r"(r1), "=r"(r2), "=r"(r3) : "r"(addr));
}
__device__ __forceinline__ void mma16816(float* d, const uint32_t* a, const uint32_t* b) {
    asm volatile(
        "mma.sync.aligned.m16n8k16.row.col.f32.bf16.bf16.f32 "
        "{%0,%1,%2,%3}, {%4,%5,%6,%7}, {%8,%9}, {%0,%1,%2,%3};"
        : "+f"(d[0]), "+f"(d[1]), "+f"(d[2]), "+f"(d[3])
        : "r"(a[0]), "r"(a[1]), "r"(a[2]), "r"(a[3]), "r"(b[0]), "r"(b[1]));
}

#define ROWB 272
#define TILE_BYTES (128 * ROWB)   // 34816
#define DSMEM_SZ (4 * TILE_BYTES) // 139264
#define STAGE_STRIDE 132          // fp32 staging row stride (words)

// ---- common fill helpers -----------------------------------------------------
__device__ __forceinline__ void fill_B_tiles(char* Bh, char* Bl,
                                             const uint4* gBh, const uint4* gBl, int tid) {
#pragma unroll
    for (int i = 0; i < 8; ++i) {
        int cidx = tid + i * 256;
        int row = cidx >> 4, c = cidx & 15;
        uint32_t off = (uint32_t)(row * ROWB + c * 16);
        *reinterpret_cast<uint4*>(Bh + off) = gBh[cidx];
        *reinterpret_cast<uint4*>(Bl + off) = gBl[cidx];
    }
}
__device__ __forceinline__ void fill_A_tiles(char* Ah, char* Al, const float* A,
                                             int m0, int M, int tid) {
#pragma unroll
    for (int i = 0; i < 8; ++i) {
        int cidx = tid + i * 256;
        int row = cidx >> 4, c = cidx & 15;
        int arow = m0 + row;
        int k0 = c * 8;
        uint32_t off = (uint32_t)(row * ROWB + c * 16);
        uint4 hv4 = make_uint4(0u, 0u, 0u, 0u), lv4 = make_uint4(0u, 0u, 0u, 0u);
        if (arow < M) {
            float4 v0 = *reinterpret_cast<const float4*>(A + (size_t)arow * HID + k0);
            float4 v1 = *reinterpret_cast<const float4*>(A + (size_t)arow * HID + k0 + 4);
            uint32_t lo;
            hv4.x = split_pair(v0.x, v0.y, lo); lv4.x = lo;
            hv4.y = split_pair(v0.z, v0.w, lo); lv4.y = lo;
            hv4.z = split_pair(v1.x, v1.y, lo); lv4.z = lo;
            hv4.w = split_pair(v1.z, v1.w, lo); lv4.w = lo;
        }
        *reinterpret_cast<uint4*>(Ah + off) = hv4;
        *reinterpret_cast<uint4*>(Al + off) = lv4;
    }
}
// convert fp32 stage rows -> bf16 hi/lo A tiles
__device__ __forceinline__ void stage_to_A_tiles(char* Ah, char* Al,
                                                 const float* stage, int tid) {
#pragma unroll
    for (int i = 0; i < 8; ++i) {
        int cidx = tid + i * 256;
        int row = cidx >> 4, c = cidx & 15;
        int k0 = c * 8;
        const float* sp = stage + row * STAGE_STRIDE + k0;
        uint32_t off = (uint32_t)(row * ROWB + c * 16);
        uint4 hv4, lv4;
        uint32_t lo;
        hv4.x = split_pair(sp[0], sp[1], lo); lv4.x = lo;
        hv4.y = split_pair(sp[2], sp[3], lo); lv4.y = lo;
        hv4.z = split_pair(sp[4], sp[5], lo); lv4.z = lo;
        hv4.w = split_pair(sp[6], sp[7], lo); lv4.w = lo;
        *reinterpret_cast<uint4*>(Ah + off) = hv4;
        *reinterpret_cast<uint4*>(Al + off) = lv4;
    }
}
// 3-pass split MMA over current smem tiles into acc
__device__ __forceinline__ void mma_3pass(float acc[2][8][4],
                                          uint32_t sAh, uint32_t sAl,
                                          uint32_t sBh, uint32_t sBl,
                                          const uint32_t a_off[2], const uint32_t b_off[4]) {
    uint32_t pa[3] = { sAh, sAl, sAh };
    uint32_t pb[3] = { sBh, sBh, sBl };
#pragma unroll
    for (int p = 0; p < 3; ++p) {
        uint32_t abase = pa[p], bbase = pb[p];
#pragma unroll
        for (int kk = 0; kk < 8; ++kk) {
            uint32_t a[2][4];
            uint32_t b[8][2];
#pragma unroll
            for (int mt = 0; mt < 2; ++mt)
                ldmatrix_x4(a[mt][0], a[mt][1], a[mt][2], a[mt][3],
                            abase + a_off[mt] + kk * 32);
#pragma unroll
            for (int bt = 0; bt < 4; ++bt)
                ldmatrix_x4(b[2 * bt][0], b[2 * bt][1], b[2 * bt + 1][0], b[2 * bt + 1][1],
                            bbase + b_off[bt] + kk * 32);
#pragma unroll
            for (int mt = 0; mt < 2; ++mt)
#pragma unroll
                for (int nt = 0; nt < 8; ++nt)
                    mma16816(acc[mt][nt], a[mt], b[nt]);
        }
    }
}
__device__ __forceinline__ void zero_acc(float acc[2][8][4]) {
#pragma unroll
    for (int a = 0; a < 2; ++a)
#pragma unroll
        for (int b = 0; b < 8; ++b)
#pragma unroll
            for (int c = 0; c < 4; ++c) acc[a][b][c] = 0.0f;
}

// ---------------- index dtype detection ------------------------------------
__global__ void detect_idx_kernel(const void* idx, int E, int* flag) {
    const long long* p = (const long long*)idx;
    int is64 = 1;
    int n = (E < 128) ? E : 128;
    for (int i = 0; i < n; ++i) {
        long long v = p[i];
        if (v < 0 || v >= NNODES) { is64 = 0; break; }
    }
    *flag = is64;
}
__device__ __forceinline__ int load_idx(const void* idx, int is64, long long pos) {
    if (is64) return (int)((const long long*)idx)[pos];
    return ((const int*)idx)[pos];
}

// ---------------- CSR build --------------------------------------------------
__global__ void hist_kernel(const void* __restrict__ idx, const int* __restrict__ flag,
                            int* __restrict__ cnt, int E) {
    int e = blockIdx.x * blockDim.x + threadIdx.x;
    if (e >= E) return;
    int dst = load_idx(idx, *flag, (long long)E + e);
    atomicAdd(&cnt[dst], 1);
}
__global__ void scan1_kernel(const int* __restrict__ cnt, int* __restrict__ off,
                             int* __restrict__ bsum, int N) {
    __shared__ int sm[1024];
    int i = blockIdx.x * 1024 + threadIdx.x;
    int v = (i < N) ? cnt[i] : 0;
    sm[threadIdx.x] = v;
    __syncthreads();
#pragma unroll
    for (int o = 1; o < 1024; o <<= 1) {
        int t = (threadIdx.x >= o) ? sm[threadIdx.x - o] : 0;
        __syncthreads();
        sm[threadIdx.x] += t;
        __syncthreads();
    }
    if (i < N) off[i] = sm[threadIdx.x] - v;   // exclusive
    if (threadIdx.x == 1023) bsum[blockIdx.x] = sm[1023];
}
__global__ void scan2_kernel(int* bsum, int nb) {
    __shared__ int sm[64];
    int t = threadIdx.x;
    int v = (t < nb) ? bsum[t] : 0;
    sm[t] = v;
    __syncthreads();
#pragma unroll
    for (int o = 1; o < 64; o <<= 1) {
        int u = (t >= o) ? sm[t - o] : 0;
        __syncthreads();
        sm[t] += u;
        __syncthreads();
    }
    if (t < nb) bsum[t] = sm[t] - v;   // exclusive
}
__global__ void scan3_kernel(int* __restrict__ off, int* __restrict__ cur,
                             const int* __restrict__ bsum,
                             const int* __restrict__ cnt,
                             float* __restrict__ inv, float* __restrict__ mask,
                             int N, int E) {
    int i = blockIdx.x * blockDim.x + threadIdx.x;
    if (i == 0) off[N] = E;
    if (i >= N) return;
    int o = off[i] + bsum[i >> 10];
    off[i] = o;
    cur[i] = o;
    int c = cnt[i];
    inv[i]  = 1.0f / (float)((c > 1) ? c : 1);
    mask[i] = (c > 0) ? 1.0f : 0.0f;
}
__global__ void scatter_kernel(const void* __restrict__ idx, const int* __restrict__ flag,
                               const float* __restrict__ eattr,
                               int* __restrict__ cur, int* __restrict__ srcs,
                               float* __restrict__ eas, int E) {
    int e = blockIdx.x * blockDim.x + threadIdx.x;
    if (e >= E) return;
    int is64 = *flag;
    int src = load_idx(idx, is64, e);
    int dst = load_idx(idx, is64, (long long)E + e);
    int p = atomicAdd(&cur[dst], 1);
    srcs[p] = src;
    eas[p]  = eattr[e];
}

// ---------------- weight prep ------------------------------------------------
__global__ void prep_weights(const float* __restrict__ mlp_W1, const float* __restrict__ mlp_W2,
                             const float* __restrict__ upd_W1, const float* __restrict__ upd_W2,
                             __nv_bfloat16* __restrict__ Wh, __nv_bfloat16* __restrict__ Wl) {
    int s = blockIdx.x;            // 0..17
    int l = s / 6, j = s % 6;
    const float* src;
    switch (j) {
        case 0:  src = mlp_W1 + (size_t)l * 257 * 128; break;
        case 1:  src = mlp_W1 + (size_t)l * 257 * 128 + 128 * 128; break;
        case 2:  src = mlp_W2 + (size_t)l * 128 * 128; break;
        case 3:  src = upd_W1 + (size_t)l * 256 * 128; break;
        case 4:  src = upd_W1 + (size_t)l * 256 * 128 + 128 * 128; break;
        default: src = upd_W2 + (size_t)l * 128 * 128; break;
    }
    uint4* dh = reinterpret_cast<uint4*>(Wh + (size_t)s * 16384);
    uint4* dl = reinterpret_cast<uint4*>(Wl + (size_t)s * 16384);
    for (int c = threadIdx.x; c < 2048; c += blockDim.x) {
        int out = c >> 4, k0 = (c & 15) * 8;
        uint32_t hv[4], lv[4];
#pragma unroll
        for (int u = 0; u < 4; ++u) {
            float a = src[(size_t)(k0 + 2 * u) * 128 + out];
            float b = src[(size_t)(k0 + 2 * u + 1) * 128 + out];
            hv[u] = split_pair(a, b, lv[u]);
        }
        dh[c] = make_uint4(hv[0], hv[1], hv[2], hv[3]);
        dl[c] = make_uint4(lv[0], lv[1], lv[2], lv[3]);
    }
}

// ---------------- V = W2 @ U1b, vb = b2 @ U1b (fp32, then split) -------------
__global__ void prep_V(const float* __restrict__ mlp_W2, const float* __restrict__ mlp_b2,
                       const float* __restrict__ upd_W1,
                       __nv_bfloat16* __restrict__ Vh, __nv_bfloat16* __restrict__ Vl,
                       float* __restrict__ vb) {
    extern __shared__ float s[];
    float* Us = s;            // 16384
    float* Vs = s + 16384;    // 16384
    int l = blockIdx.x;
    int tid = threadIdx.x;
    const float* W2  = mlp_W2 + (size_t)l * 16384;
    const float* U1b = upd_W1 + (size_t)l * 256 * 128 + 128 * 128;
    const float* b2  = mlp_b2 + (size_t)l * 128;
    for (int i = tid; i < 16384; i += 256) Us[i] = U1b[i];
    __syncthreads();
    for (int idx = tid; idx < 16384; idx += 256) {
        int k = idx >> 7, j = idx & 127;
        float acc = 0.0f;
        const float* wr = W2 + k * 128;
#pragma unroll 8
        for (int m = 0; m < 128; ++m) acc = fmaf(wr[m], Us[m * 128 + j], acc);
        Vs[idx] = acc;
    }
    if (tid < 128) {
        float a = 0.0f;
#pragma unroll 8
        for (int k = 0; k < 128; ++k) a = fmaf(b2[k], Us[k * 128 + tid], a);
        vb[l * 128 + tid] = a;
    }
    __syncthreads();
    uint4* dh = reinterpret_cast<uint4*>(Vh + (size_t)l * 16384);
    uint4* dl = reinterpret_cast<uint4*>(Vl + (size_t)l * 16384);
    for (int c = tid; c < 2048; c += 256) {
        int out = c >> 4, k0 = (c & 15) * 8;
        uint32_t hv[4], lv[4];
#pragma unroll
        for (int u = 0; u < 4; ++u) {
            float a = Vs[(k0 + 2 * u) * 128 + out];
            float b = Vs[(k0 + 2 * u + 1) * 128 + out];
            hv[u] = split_pair(a, b, lv[u]);
        }
        dh[c] = make_uint4(hv[0], hv[1], hv[2], hv[3]);
        dl[c] = make_uint4(lv[0], lv[1], lv[2], lv[3]);
    }
}

// ---------------- fused encoder + layer-0 message GEMMs ----------------------
__global__ __launch_bounds__(256) void enc_msg_kernel(
    const float* __restrict__ nf, const float* __restrict__ encW,
    const float* __restrict__ encb,
    const __nv_bfloat16* __restrict__ W1ah, const __nv_bfloat16* __restrict__ W1al,
    const __nv_bfloat16* __restrict__ W1bh, const __nv_bfloat16* __restrict__ W1bl,
    const float* __restrict__ b1,
    float* __restrict__ Xout, float* __restrict__ Aout, float* __restrict__ Bout, int M)
{
    extern __shared__ char sm[];
    char* Ah = sm;
    char* Al = sm + TILE_BYTES;
    char* Bh = sm + 2 * TILE_BYTES;
    char* Bl = sm + 3 * TILE_BYTES;
    float* stage = reinterpret_cast<float*>(Bh);
    const uint32_t sAh = smem_to_u32(Ah), sAl = smem_to_u32(Al);
    const uint32_t sBh = smem_to_u32(Bh), sBl = smem_to_u32(Bl);

    const int tid  = threadIdx.x;
    const int wid  = tid >> 5;
    const int lane = tid & 31;
    const int warp_m = wid & 3;
    const int warp_n = wid >> 2;
    const int m0 = blockIdx.x * 128;

    uint32_t a_off[2], b_off[4];
#pragma unroll
    for (int mt = 0; mt < 2; ++mt)
        a_off[mt] = (uint32_t)((warp_m * 32 + mt * 16 + (lane & 15)) * ROWB + (lane >> 4) * 16);
#pragma unroll
    for (int bt = 0; bt < 4; ++bt)
        b_off[bt] = (uint32_t)((warp_n * 64 + bt * 16 + ((lane >> 4) & 1) * 8 + (lane & 7)) * ROWB
                               + ((lane >> 3) & 1) * 16);

    // ---- encoder: x rows into stage (and Xout) ----
    {
        int pc = tid & 63;           // column pair
        int rg = tid >> 6;           // row group (x32)
        int col0 = pc * 2;
        float w0[5], w1[5];
#pragma unroll
        for (int k = 0; k < 5; ++k) {
            w0[k] = encW[k * 128 + col0];
            w1[k] = encW[k * 128 + col0 + 1];
        }
        float bb0 = encb[col0], bb1 = encb[col0 + 1];
#pragma unroll 1
        for (int rr = 0; rr < 32; ++rr) {
            int lr = rg * 32 + rr;
            int r = m0 + lr;
            float v0 = 0.0f, v1 = 0.0f;
            if (r < M) {
                v0 = bb0; v1 = bb1;
#pragma unroll
                for (int k = 0; k < 5; ++k) {
                    float nv = nf[(size_t)r * 5 + k];
                    v0 = fmaf(nv, w0[k], v0);
                    v1 = fmaf(nv, w1[k], v1);
                }
                *reinterpret_cast<float2*>(Xout + (size_t)r * HID + col0) = make_float2(v0, v1);
            }
            stage[lr * STAGE_STRIDE + col0]     = v0;
            stage[lr * STAGE_STRIDE + col0 + 1] = v1;
        }
    }
    __syncthreads();
    stage_to_A_tiles(Ah, Al, stage, tid);
    __syncthreads();   // conversion reads stage (aliases B) before B fill

    float acc[2][8][4];
#pragma unroll 1
    for (int j = 0; j < 2; ++j) {
        if (j) __syncthreads();
        fill_B_tiles(Bh, Bl,
                     reinterpret_cast<const uint4*>(j ? W1bh : W1ah),
                     reinterpret_cast<const uint4*>(j ? W1bl : W1al), tid);
        __syncthreads();
        zero_acc(acc);
        mma_3pass(acc, sAh, sAl, sBh, sBl, a_off, b_off);
        float* C = j ? Bout : Aout;
        const float* bias = j ? nullptr : b1;
#pragma unroll
        for (int mt = 0; mt < 2; ++mt) {
            int r0 = m0 + warp_m * 32 + mt * 16 + (lane >> 2);
#pragma unroll
            for (int half = 0; half < 2; ++half) {
                int r = r0 + half * 8;
                if (r >= M) continue;
#pragma unroll
                for (int nt = 0; nt < 8; ++nt) {
                    int col = warp_n * 64 + nt * 8 + (lane & 3) * 2;
                    float v0 = acc[mt][nt][2 * half + 0];
                    float v1 = acc[mt][nt][2 * half + 1];
                    if (bias != nullptr) { v0 += bias[col]; v1 += bias[col + 1]; }
                    *reinterpret_cast<float2*>(C + (size_t)r * HID + col) = make_float2(v0, v1);
                }
            }
        }
    }
}

// ---------------- fused layer: update + LN + next-layer message GEMMs --------
// acc1 = X@U1a + S@V ; h = relu(acc1 + ub1 + mask*vb) ; xn = h@U2 + ub2
// x = relu(LN(xn)) -> Xout ; if W1ah: Aout = x@W1a + b1n ; Bout = x@W1b
__global__ __launch_bounds__(256) void layer_kernel(
    const float* __restrict__ X, const float* __restrict__ S,
    const float* __restrict__ mask,
    const __nv_bfloat16* __restrict__ U1ah, const __nv_bfloat16* __restrict__ U1al,
    const __nv_bfloat16* __restrict__ Vh, const __nv_bfloat16* __restrict__ Vl,
    const float* __restrict__ ub1, const float* __restrict__ vb,
    const __nv_bfloat16* __restrict__ U2h, const __nv_bfloat16* __restrict__ U2l,
    const float* __restrict__ ub2,
    const float* __restrict__ lng, const float* __restrict__ lnb,
    const __nv_bfloat16* __restrict__ W1ah, const __nv_bfloat16* __restrict__ W1al,
    const __nv_bfloat16* __restrict__ W1bh, const __nv_bfloat16* __restrict__ W1bl,
    const float* __restrict__ b1n,
    float* __restrict__ Xout, float* __restrict__ Aout, float* __restrict__ Bout, int M)
{
    extern __shared__ char sm[];
    char* Ah = sm;
    char* Al = sm + TILE_BYTES;
    char* Bh = sm + 2 * TILE_BYTES;
    char* Bl = sm + 3 * TILE_BYTES;
    float* stage = reinterpret_cast<float*>(Bh);
    const uint32_t sAh = smem_to_u32(Ah), sAl = smem_to_u32(Al);
    const uint32_t sBh = smem_to_u32(Bh), sBl = smem_to_u32(Bl);

    const int tid  = threadIdx.x;
    const int wid  = tid >> 5;
    const int lane = tid & 31;
    const int warp_m = wid & 3;
    const int warp_n = wid >> 2;
    const int m0 = blockIdx.x * 128;

    uint32_t a_off[2], b_off[4];
#pragma unroll
    for (int mt = 0; mt < 2; ++mt)
        a_off[mt] = (uint32_t)((warp_m * 32 + mt * 16 + (lane & 15)) * ROWB + (lane >> 4) * 16);
#pragma unroll
    for (int bt = 0; bt < 4; ++bt)
        b_off[bt] = (uint32_t)((warp_n * 64 + bt * 16 + ((lane >> 4) & 1) * 8 + (lane & 7)) * ROWB
                               + ((lane >> 3) & 1) * 16);

    // ---- stage 1: acc = X@U1a + S@V ----
    float acc[2][8][4];
    zero_acc(acc);
#pragma unroll 1
    for (int s = 0; s < 2; ++s) {
        if (s) __syncthreads();
        fill_A_tiles(Ah, Al, s ? S : X, m0, M, tid);
        fill_B_tiles(Bh, Bl,
                     reinterpret_cast<const uint4*>(s ? Vh : U1ah),
                     reinterpret_cast<const uint4*>(s ? Vl : U1al), tid);
        __syncthreads();
        mma_3pass(acc, sAh, sAl, sBh, sBl, a_off, b_off);
    }

    // ---- h = relu(acc + ub1 + mask*vb) -> A tiles ----
    __syncthreads();
#pragma unroll
    for (int mt = 0; mt < 2; ++mt) {
#pragma unroll
        for (int half = 0; half < 2; ++half) {
            int lr = warp_m * 32 + mt * 16 + (lane >> 2) + half * 8;
            int r = m0 + lr;
            float mk = (r < M) ? mask[r] : 0.0f;
#pragma unroll
            for (int nt = 0; nt < 8; ++nt) {
                int col = warp_n * 64 + nt * 8 + (lane & 3) * 2;
                float v0 = fmaxf(acc[mt][nt][2 * half + 0] + ub1[col + 0] + mk * vb[col + 0], 0.0f);
                float v1 = fmaxf(acc[mt][nt][2 * half + 1] + ub1[col + 1] + mk * vb[col + 1], 0.0f);
                uint32_t lo;
                uint32_t hi = split_pair(v0, v1, lo);
                uint32_t off = (uint32_t)(lr * ROWB + col * 2);
                *reinterpret_cast<uint32_t*>(Ah + off) = hi;
                *reinterpret_cast<uint32_t*>(Al + off) = lo;
            }
        }
    }
    // ---- stage 2: xn = h@U2 ----
    fill_B_tiles(Bh, Bl, reinterpret_cast<const uint4*>(U2h),
                 reinterpret_cast<const uint4*>(U2l), tid);
    __syncthreads();
    zero_acc(acc);
    mma_3pass(acc, sAh, sAl, sBh, sBl, a_off, b_off);

    // ---- epilogue: + ub2 -> stage (aliases B; safe after mma done) ----
    __syncthreads();
#pragma unroll
    for (int mt = 0; mt < 2; ++mt) {
#pragma unroll
        for (int half = 0; half < 2; ++half) {
            int lr = warp_m * 32 + mt * 16 + (lane >> 2) + half * 8;
#pragma unroll
            for (int nt = 0; nt < 8; ++nt) {
                int col = warp_n * 64 + nt * 8 + (lane & 3) * 2;
                *reinterpret_cast<float2*>(stage + lr * STAGE_STRIDE + col) =
                    make_float2(acc[mt][nt][2 * half + 0] + ub2[col + 0],
                                acc[mt][nt][2 * half + 1] + ub2[col + 1]);
            }
        }
    }
    __syncthreads();

    // ---- LN + relu: write Xout, keep normalized rows in stage ----
#pragma unroll 1
    for (int i = 0; i < 16; ++i) {
        int lr = wid * 16 + i;
        int r = m0 + lr;
        if (r >= M) break;
        float4 v = *reinterpret_cast<const float4*>(stage + lr * STAGE_STRIDE + lane * 4);
        float ssum = v.x + v.y + v.z + v.w;
#pragma unroll
        for (int o = 16; o > 0; o >>= 1) ssum += __shfl_xor_sync(0xffffffffu, ssum, o);
        float mu = ssum * (1.0f / 128.0f);
        float dx = v.x - mu, dy = v.y - mu, dz = v.z - mu, dw = v.w - mu;
        float q = dx * dx + dy * dy + dz * dz + dw * dw;
#pragma unroll
        for (int o = 16; o > 0; o >>= 1) q += __shfl_xor_sync(0xffffffffu, q, o);
        float rsd = rsqrtf(q * (1.0f / 128.0f) + 1e-5f);
        float4 gg = *reinterpret_cast<const float4*>(lng + lane * 4);
        float4 bb = *reinterpret_cast<const float4*>(lnb + lane * 4);
        float4 rr;
        rr.x = fmaxf(fmaf(dx * rsd, gg.x, bb.x), 0.0f);
        rr.y = fmaxf(fmaf(dy * rsd, gg.y, bb.y), 0.0f);
        rr.z = fmaxf(fmaf(dz * rsd, gg.z, bb.z), 0.0f);
        rr.w = fmaxf(fmaf(dw * rsd, gg.w, bb.w), 0.0f);
        *reinterpret_cast<float4*>(Xout + (size_t)r * HID + lane * 4) = rr;
        *reinterpret_cast<float4*>(stage + lr * STAGE_STRIDE + lane * 4) = rr;
    }

    // ---- optional: next-layer message GEMMs from stage ----
    if (W1ah != nullptr) {
        __syncthreads();
        stage_to_A_tiles(Ah, Al, stage, tid);
        __syncthreads();   // stage (aliases B) fully read before B refill
#pragma unroll 1
        for (int j = 0; j < 2; ++j) {
            if (j) __syncthreads();
            fill_B_tiles(Bh, Bl,
                         reinterpret_cast<const uint4*>(j ? W1bh : W1ah),
                         reinterpret_cast<const uint4*>(j ? W1bl : W1al), tid);
            __syncthreads();
            zero_acc(acc);
            mma_3pass(acc, sAh, sAl, sBh, sBl, a_off, b_off);
            float* C = j ? Bout : Aout;
            const float* bias = j ? nullptr : b1n;
#pragma unroll
            for (int mt = 0; mt < 2; ++mt) {
                int r0 = m0 + warp_m * 32 + mt * 16 + (lane >> 2);
#pragma unroll
                for (int half = 0; half < 2; ++half) {
                    int r = r0 + half * 8;
                    if (r >= M) continue;
#pragma unroll
                    for (int nt = 0; nt < 8; ++nt) {
                        int col = warp_n * 64 + nt * 8 + (lane & 3) * 2;
                        float v0 = acc[mt][nt][2 * half + 0];
                        float v1 = acc[mt][nt][2 * half + 1];
                        if (bias != nullptr) { v0 += bias[col]; v1 += bias[col + 1]; }
                        *reinterpret_cast<float2*>(C + (size_t)r * HID + col) =
                            make_float2(v0, v1);
                    }
                }
            }
        }
    }
}

// ---------------- CSR aggregation (writes inv-scaled sum) --------------------
__global__ __launch_bounds__(256) void agg_kernel(
    const float* __restrict__ A, const float* __restrict__ B,
    const int* __restrict__ srcs, const float* __restrict__ eas,
    const int* __restrict__ off, const float* __restrict__ cvec,
    const float* __restrict__ inv,
    float* __restrict__ S, int N)
{
    int node = (blockIdx.x * blockDim.x + threadIdx.x) >> 5;
    if (node >= N) return;
    int lane = threadIdx.x & 31;
    const float4 a = *reinterpret_cast<const float4*>(A + (size_t)node * HID + lane * 4);
    const float4 c = *reinterpret_cast<const float4*>(cvec + lane * 4);
    float4 s = make_float4(0.f, 0.f, 0.f, 0.f);
    int p  = off[node];
    int pe = off[node + 1];
    for (; p + 1 < pe; p += 2) {
        int s0 = srcs[p], s1 = srcs[p + 1];
        float e0 = eas[p], e1 = eas[p + 1];
        const float4 b0 = *reinterpret_cast<const float4*>(B + (size_t)s0 * HID + lane * 4);
        const float4 b1 = *reinterpret_cast<const float4*>(B + (size_t)s1 * HID + lane * 4);
        s.x += fmaxf(fmaf(e0, c.x, a.x + b0.x), 0.0f) + fmaxf(fmaf(e1, c.x, a.x + b1.x), 0.0f);
        s.y += fmaxf(fmaf(e0, c.y, a.y + b0.y), 0.0f) + fmaxf(fmaf(e1, c.y, a.y + b1.y), 0.0f);
        s.z += fmaxf(fmaf(e0, c.z, a.z + b0.z), 0.0f) + fmaxf(fmaf(e1, c.z, a.z + b1.z), 0.0f);
        s.w += fmaxf(fmaf(e0, c.w, a.w + b0.w), 0.0f) + fmaxf(fmaf(e1, c.w, a.w + b1.w), 0.0f);
    }
    if (p < pe) {
        int s0 = srcs[p];
        float e0 = eas[p];
        const float4 b0 = *reinterpret_cast<const float4*>(B + (size_t)s0 * HID + lane * 4);
        s.x += fmaxf(fmaf(e0, c.x, a.x + b0.x), 0.0f);
        s.y += fmaxf(fmaf(e0, c.y, a.y + b0.y), 0.0f);
        s.z += fmaxf(fmaf(e0, c.z, a.z + b0.z), 0.0f);
        s.w += fmaxf(fmaf(e0, c.w, a.w + b0.w), 0.0f);
    }
    float iv = inv[node];
    s.x *= iv; s.y *= iv; s.z *= iv; s.w *= iv;
    *reinterpret_cast<float4*>(S + (size_t)node * HID + lane * 4) = s;
}

// ---------------- column sum + head ------------------------------------------
__global__ void colsum_kernel(const float* __restrict__ x, float* __restrict__ cs, int N) {
    int col = threadIdx.x & 127;
    int rg  = threadIdx.x >> 7;
    float s = 0.0f;
    for (int row = blockIdx.x * 2 + rg; row < N; row += gridDim.x * 2)
        s += x[(size_t)row * HID + col];
    atomicAdd(&cs[col], s);
}
__global__ void head_kernel(const float* __restrict__ cs,
                            const float* __restrict__ W1, const float* __restrict__ b1,
                            const float* __restrict__ W2, const float* __restrict__ b2,
                            float* __restrict__ out, float invN)
{
    __shared__ float g[HID], h[HID];
    int t = threadIdx.x;
    g[t] = cs[t] * invN;
    __syncthreads();
    float acc = b1[t];
#pragma unroll 8
    for (int k = 0; k < HID; ++k) acc = fmaf(g[k], W1[k * HID + t], acc);
    h[t] = fmaxf(acc, 0.0f);
    __syncthreads();
    float o = b2[t];
#pragma unroll 8
    for (int k = 0; k < HID; ++k) o = fmaf(h[k], W2[k * HID + t], o);
    out[t] = o;
}

// ---------------- launch ----------------------------------------------------
extern "C" void kernel_launch(void* const* d_in, const int* in_sizes, int n_in,
                              void* d_out, int out_size) {
    const float* node_feat = (const float*)d_in[0];
    const float* edge_attr = (const float*)d_in[1];
    const float* enc_W     = (const float*)d_in[2];
    const float* enc_b     = (const float*)d_in[3];
    const float* mlp_W1    = (const float*)d_in[4];
    const float* mlp_b1    = (const float*)d_in[5];
    const float* mlp_W2    = (const float*)d_in[6];
    const float* mlp_b2    = (const float*)d_in[7];
    const float* upd_W1    = (const float*)d_in[8];
    const float* upd_b1    = (const float*)d_in[9];
    const float* upd_W2    = (const float*)d_in[10];
    const float* upd_b2    = (const float*)d_in[11];
    const float* ln_g      = (const float*)d_in[12];
    const float* ln_b      = (const float*)d_in[13];
    const float* out_W1    = (const float*)d_in[14];
    const float* out_b1    = (const float*)d_in[15];
    const float* out_W2    = (const float*)d_in[16];
    const float* out_b2    = (const float*)d_in[17];
    const void*  edge_idx  = d_in[18];

    const int N = in_sizes[0] / 5;
    const int E = in_sizes[18] / 2;

    float *px, *pA, *pB, *pS, *pinv, *pmask, *pcs, *peas, *pvb;
    int *pflag, *pcnt, *poff, *pcur, *pbsum, *psrcs;
    __nv_bfloat16 *pWh, *pWl, *pVh, *pVl;
    cudaGetSymbolAddress((void**)&px,    g_x);
    cudaGetSymbolAddress((void**)&pA,    g_A);
    cudaGetSymbolAddress((void**)&pB,    g_B);
    cudaGetSymbolAddress((void**)&pS,    g_S);
    cudaGetSymbolAddress((void**)&pinv,  g_inv);
    cudaGetSymbolAddress((void**)&pmask, g_mask);
    cudaGetSymbolAddress((void**)&pcs,   g_colsum);
    cudaGetSymbolAddress((void**)&pflag, g_is64);
    cudaGetSymbolAddress((void**)&pcnt,  g_cnt);
    cudaGetSymbolAddress((void**)&poff,  g_off);
    cudaGetSymbolAddress((void**)&pcur,  g_cur);
    cudaGetSymbolAddress((void**)&pbsum, g_bsum);
    cudaGetSymbolAddress((void**)&psrcs, g_srcs);
    cudaGetSymbolAddress((void**)&peas,  g_eas);
    cudaGetSymbolAddress((void**)&pWh,   g_Wh);
    cudaGetSymbolAddress((void**)&pWl,   g_Wl);
    cudaGetSymbolAddress((void**)&pVh,   g_Vh);
    cudaGetSymbolAddress((void**)&pVl,   g_Vl);
    cudaGetSymbolAddress((void**)&pvb,   g_vb);

    cudaFuncSetAttribute(enc_msg_kernel, cudaFuncAttributeMaxDynamicSharedMemorySize, DSMEM_SZ);
    cudaFuncSetAttribute(layer_kernel,   cudaFuncAttributeMaxDynamicSharedMemorySize, DSMEM_SZ);
    cudaFuncSetAttribute(prep_V,         cudaFuncAttributeMaxDynamicSharedMemorySize, 131072);

    const int gemm_grid = (N + 127) / 128;
    const int scan_blocks = (N + 1023) / 1024;

    // order chosen so launch #5 (ncu -s 5 -c 1) is the big fused GEMM kernel
    detect_idx_kernel<<<1, 1>>>(edge_idx, E, pflag);                               // 0
    prep_weights<<<18, 256>>>(mlp_W1, mlp_W2, upd_W1, upd_W2, pWh, pWl);           // 1
    prep_V<<<3, 256, 131072>>>(mlp_W2, mlp_b2, upd_W1, pVh, pVl, pvb);             // 2
    cudaMemsetAsync(pcnt, 0, (size_t)N * sizeof(int));                             // 3
    hist_kernel<<<(E + 255) / 256, 256>>>(edge_idx, pflag, pcnt, E);               // 4
    enc_msg_kernel<<<gemm_grid, 256, DSMEM_SZ>>>(node_feat, enc_W, enc_b,          // 5
        pWh + 0 * 16384, pWl + 0 * 16384, pWh + 1 * 16384, pWl + 1 * 16384,
        mlp_b1, px, pA, pB, N);
    scan1_kernel<<<scan_blocks, 1024>>>(pcnt, poff, pbsum, N);
    scan2_kernel<<<1, 64>>>(pbsum, scan_blocks);
    scan3_kernel<<<(N + 255) / 256, 256>>>(poff, pcur, pbsum, pcnt, pinv, pmask, N, E);
    scatter_kernel<<<(E + 255) / 256, 256>>>(edge_idx, pflag, edge_attr, pcur, psrcs, peas, E);

    for (int l = 0; l < 3; ++l) {
        const float* cve = mlp_W1 + (size_t)l * 257 * HID + 256 * HID;
        const float* ub1 = upd_b1 + (size_t)l * HID;
        const float* ub2 = upd_b2 + (size_t)l * HID;
        __nv_bfloat16* U1a_h = pWh + (size_t)(l * 6 + 3) * 16384;
        __nv_bfloat16* U1a_l = pWl + (size_t)(l * 6 + 3) * 16384;
        __nv_bfloat16* U2_h  = pWh + (size_t)(l * 6 + 5) * 16384;
        __nv_bfloat16* U2_l  = pWl + (size_t)(l * 6 + 5) * 16384;
        const int ln = l + 1;   // next layer (for fused msg GEMMs)
        const bool has_next = (l < 2);
        __nv_bfloat16* nW1a_h = has_next ? pWh + (size_t)(ln * 6 + 0) * 16384 : nullptr;
        __nv_bfloat16* nW1a_l = has_next ? pWl + (size_t)(ln * 6 + 0) * 16384 : nullptr;
        __nv_bfloat16* nW1b_h = has_next ? pWh + (size_t)(ln * 6 + 1) * 16384 : nullptr;
        __nv_bfloat16* nW1b_l = has_next ? pWl + (size_t)(ln * 6 + 1) * 16384 : nullptr;
        const float* nb1 = has_next ? mlp_b1 + (size_t)ln * HID : nullptr;

        // S[i] = inv[i] * sum over CSR adj of relu(A[i]+B[src]+ea*c)
        agg_kernel<<<(N * 32 + 255) / 256, 256>>>(pA, pB, psrcs, peas, poff, cve, pinv, pS, N);

        // update + LN (+ next-layer msg GEMMs)
        layer_kernel<<<gemm_grid, 256, DSMEM_SZ>>>(px, pS, pmask,
            U1a_h, U1a_l, pVh + (size_t)l * 16384, pVl + (size_t)l * 16384,
            ub1, pvb + (size_t)l * HID, U2_h, U2_l, ub2,
            ln_g + (size_t)l * HID, ln_b + (size_t)l * HID,
            nW1a_h, nW1a_l, nW1b_h, nW1b_l, nb1,
            px, pA, pB, N);
    }

    cudaMemsetAsync(pcs, 0, HID * sizeof(float));
    colsum_kernel<<<128, 256>>>(px, pcs, N);
    head_kernel<<<1, HID>>>(pcs, out_W1, out_b1, out_W2, out_b2,
                            (float*)d_out, 1.0f / (float)N);
}

// round 13
// speedup vs baseline: 1.0087x; 1.0087x over previous
#include <cuda_runtime.h>
#include <cuda_bf16.h>
#include <cstdint>

#define NNODES 50000
#define NEDGES 800000
#define HID    128

// ---------------- scratch (device globals; no allocation allowed) ----------
__device__ float g_x[NNODES * HID];
__device__ float g_A[NNODES * HID];
__device__ float g_B[NNODES * HID];
__device__ float g_S[NNODES * HID];
__device__ float g_inv[NNODES];
__device__ float g_mask[NNODES];
__device__ float g_colsum[HID];
__device__ int   g_is64;
// CSR by dst
__device__ int   g_cnt[NNODES];
__device__ int   g_off[NNODES + 1];
__device__ int   g_cur[NNODES];
__device__ int   g_bsum[64];
__device__ int   g_srcs[NEDGES];
__device__ float g_eas[NEDGES];
// 18 weight slices (3 layers x {W1a,W1b,W2,U1a,U1b,U2}), each 128x128 bf16,
// transposed ([out][k], packed row-major), hi and lo parts.
__device__ __nv_bfloat16 g_Wh[18 * 16384];
__device__ __nv_bfloat16 g_Wl[18 * 16384];
// V = W2 @ U1b per layer (hi/lo images) and vb = b2 @ U1b
__device__ __nv_bfloat16 g_Vh[3 * 16384];
__device__ __nv_bfloat16 g_Vl[3 * 16384];
__device__ float g_vb[3 * 128];

// ---------------- helpers ----------------------------------------------------
__device__ __forceinline__ uint32_t smem_to_u32(const void* smem_ptr) {
    uint32_t addr;
    asm("{ .reg .u64 tmp; cvta.to.shared.u64 tmp, %1; cvt.u32.u64 %0, tmp; }"
        : "=r"(addr) : "l"(smem_ptr));
    return addr;
}
__device__ __forceinline__ uint32_t split_pair(float a, float b, uint32_t& lo) {
    __nv_bfloat16 ha = __float2bfloat16(a), hb = __float2bfloat16(b);
    __nv_bfloat16 la = __float2bfloat16(a - __bfloat162float(ha));
    __nv_bfloat16 lb = __float2bfloat16(b - __bfloat162float(hb));
    lo = (uint32_t)__bfloat16_as_ushort(la) | ((uint32_t)__bfloat16_as_ushort(lb) << 16);
    return (uint32_t)__bfloat16_as_ushort(ha) | ((uint32_t)__bfloat16_as_ushort(hb) << 16);
}
__device__ __forceinline__ void ldmatrix_x4(uint32_t& r0, uint32_t& r1,
                                            uint32_t& r2, uint32_t& r3, uint32_t addr) {
    asm volatile("ldmatrix.sync.aligned.m8n8.x4.shared.b16 {%0,%1,%2,%3}, [%4];"
                 : "=r"(r0), "=r"(r1), "=r"(r2), "=r"(r3) : "r"(addr));
}
__device__ __forceinline__ void mma16816(float* d, const uint32_t* a, const uint32_t* b) {
    asm volatile(
        "mma.sync.aligned.m16n8k16.row.col.f32.bf16.bf16.f32 "
        "{%0,%1,%2,%3}, {%4,%5,%6,%7}, {%8,%9}, {%0,%1,%2,%3};"
        : "+f"(d[0]), "+f"(d[1]), "+f"(d[2]), "+f"(d[3])
        : "r"(a[0]), "r"(a[1]), "r"(a[2]), "r"(a[3]), "r"(b[0]), "r"(b[1]));
}

#define ROWB 272
#define TILE_BYTES (128 * ROWB)   // 34816
#define DSMEM_SZ (4 * TILE_BYTES) // 139264
#define STAGE_STRIDE 132          // fp32 staging row stride (words)

// ---- common fill helpers -----------------------------------------------------
__device__ __forceinline__ void fill_B_tiles(char* Bh, char* Bl,
                                             const uint4* gBh, const uint4* gBl, int tid) {
#pragma unroll
    for (int i = 0; i < 8; ++i) {
        int cidx = tid + i * 256;
        int row = cidx >> 4, c = cidx & 15;
        uint32_t off = (uint32_t)(row * ROWB + c * 16);
        *reinterpret_cast<uint4*>(Bh + off) = gBh[cidx];
        *reinterpret_cast<uint4*>(Bl + off) = gBl[cidx];
    }
}
__device__ __forceinline__ void fill_A_tiles(char* Ah, char* Al, const float* A,
                                             int m0, int M, int tid) {
#pragma unroll
    for (int i = 0; i < 8; ++i) {
        int cidx = tid + i * 256;
        int row = cidx >> 4, c = cidx & 15;
        int arow = m0 + row;
        int k0 = c * 8;
        uint32_t off = (uint32_t)(row * ROWB + c * 16);
        uint4 hv4 = make_uint4(0u, 0u, 0u, 0u), lv4 = make_uint4(0u, 0u, 0u, 0u);
        if (arow < M) {
            float4 v0 = *reinterpret_cast<const float4*>(A + (size_t)arow * HID + k0);
            float4 v1 = *reinterpret_cast<const float4*>(A + (size_t)arow * HID + k0 + 4);
            uint32_t lo;
            hv4.x = split_pair(v0.x, v0.y, lo); lv4.x = lo;
            hv4.y = split_pair(v0.z, v0.w, lo); lv4.y = lo;
            hv4.z = split_pair(v1.x, v1.y, lo); lv4.z = lo;
            hv4.w = split_pair(v1.z, v1.w, lo); lv4.w = lo;
        }
        *reinterpret_cast<uint4*>(Ah + off) = hv4;
        *reinterpret_cast<uint4*>(Al + off) = lv4;
    }
}
// 3-pass split MMA over current smem tiles into acc
__device__ __forceinline__ void mma_3pass(float acc[2][8][4],
                                          uint32_t sAh, uint32_t sAl,
                                          uint32_t sBh, uint32_t sBl,
                                          const uint32_t a_off[2], const uint32_t b_off[4]) {
    uint32_t pa[3] = { sAh, sAl, sAh };
    uint32_t pb[3] = { sBh, sBh, sBl };
#pragma unroll
    for (int p = 0; p < 3; ++p) {
        uint32_t abase = pa[p], bbase = pb[p];
#pragma unroll
        for (int kk = 0; kk < 8; ++kk) {
            uint32_t a[2][4];
            uint32_t b[8][2];
#pragma unroll
            for (int mt = 0; mt < 2; ++mt)
                ldmatrix_x4(a[mt][0], a[mt][1], a[mt][2], a[mt][3],
                            abase + a_off[mt] + kk * 32);
#pragma unroll
            for (int bt = 0; bt < 4; ++bt)
                ldmatrix_x4(b[2 * bt][0], b[2 * bt][1], b[2 * bt + 1][0], b[2 * bt + 1][1],
                            bbase + b_off[bt] + kk * 32);
#pragma unroll
            for (int mt = 0; mt < 2; ++mt)
#pragma unroll
                for (int nt = 0; nt < 8; ++nt)
                    mma16816(acc[mt][nt], a[mt], b[nt]);
        }
    }
}
__device__ __forceinline__ void zero_acc(float acc[2][8][4]) {
#pragma unroll
    for (int a = 0; a < 2; ++a)
#pragma unroll
        for (int b = 0; b < 8; ++b)
#pragma unroll
            for (int c = 0; c < 4; ++c) acc[a][b][c] = 0.0f;
}

// ---------------- index dtype detection ------------------------------------
__global__ void detect_idx_kernel(const void* idx, int E, int* flag) {
    const long long* p = (const long long*)idx;
    int is64 = 1;
    int n = (E < 128) ? E : 128;
    for (int i = 0; i < n; ++i) {
        long long v = p[i];
        if (v < 0 || v >= NNODES) { is64 = 0; break; }
    }
    *flag = is64;
}
__device__ __forceinline__ int load_idx(const void* idx, int is64, long long pos) {
    if (is64) return (int)((const long long*)idx)[pos];
    return ((const int*)idx)[pos];
}

// ---------------- CSR build --------------------------------------------------
__global__ void hist_kernel(const void* __restrict__ idx, const int* __restrict__ flag,
                            int* __restrict__ cnt, int E) {
    int e = blockIdx.x * blockDim.x + threadIdx.x;
    if (e >= E) return;
    int dst = load_idx(idx, *flag, (long long)E + e);
    atomicAdd(&cnt[dst], 1);
}
__global__ void scan1_kernel(const int* __restrict__ cnt, int* __restrict__ off,
                             int* __restrict__ bsum, int N) {
    __shared__ int sm[1024];
    int i = blockIdx.x * 1024 + threadIdx.x;
    int v = (i < N) ? cnt[i] : 0;
    sm[threadIdx.x] = v;
    __syncthreads();
#pragma unroll
    for (int o = 1; o < 1024; o <<= 1) {
        int t = (threadIdx.x >= o) ? sm[threadIdx.x - o] : 0;
        __syncthreads();
        sm[threadIdx.x] += t;
        __syncthreads();
    }
    if (i < N) off[i] = sm[threadIdx.x] - v;   // exclusive
    if (threadIdx.x == 1023) bsum[blockIdx.x] = sm[1023];
}
__global__ void scan2_kernel(int* bsum, int nb) {
    __shared__ int sm[64];
    int t = threadIdx.x;
    int v = (t < nb) ? bsum[t] : 0;
    sm[t] = v;
    __syncthreads();
#pragma unroll
    for (int o = 1; o < 64; o <<= 1) {
        int u = (t >= o) ? sm[t - o] : 0;
        __syncthreads();
        sm[t] += u;
        __syncthreads();
    }
    if (t < nb) bsum[t] = sm[t] - v;   // exclusive
}
__global__ void scan3_kernel(int* __restrict__ off, int* __restrict__ cur,
                             const int* __restrict__ bsum,
                             const int* __restrict__ cnt,
                             float* __restrict__ inv, float* __restrict__ mask,
                             int N, int E) {
    int i = blockIdx.x * blockDim.x + threadIdx.x;
    if (i == 0) off[N] = E;
    if (i >= N) return;
    int o = off[i] + bsum[i >> 10];
    off[i] = o;
    cur[i] = o;
    int c = cnt[i];
    inv[i]  = 1.0f / (float)((c > 1) ? c : 1);
    mask[i] = (c > 0) ? 1.0f : 0.0f;
}
__global__ void scatter_kernel(const void* __restrict__ idx, const int* __restrict__ flag,
                               const float* __restrict__ eattr,
                               int* __restrict__ cur, int* __restrict__ srcs,
                               float* __restrict__ eas, int E) {
    int e = blockIdx.x * blockDim.x + threadIdx.x;
    if (e >= E) return;
    int is64 = *flag;
    int src = load_idx(idx, is64, e);
    int dst = load_idx(idx, is64, (long long)E + e);
    int p = atomicAdd(&cur[dst], 1);
    srcs[p] = src;
    eas[p]  = eattr[e];
}

// ---------------- encoder ----------------------------------------------------
__global__ void encoder_kernel(const float* __restrict__ nf, const float* __restrict__ W,
                               const float* __restrict__ b, float* __restrict__ x, int N) {
    int i = blockIdx.x * blockDim.x + threadIdx.x;
    if (i >= N * HID) return;
    int n = i >> 7;
    int h = i & 127;
    float acc = b[h];
#pragma unroll
    for (int k = 0; k < 5; ++k)
        acc = fmaf(nf[n * 5 + k], W[k * HID + h], acc);
    x[i] = acc;
}

// ---------------- weight prep ------------------------------------------------
__global__ void prep_weights(const float* __restrict__ mlp_W1, const float* __restrict__ mlp_W2,
                             const float* __restrict__ upd_W1, const float* __restrict__ upd_W2,
                             __nv_bfloat16* __restrict__ Wh, __nv_bfloat16* __restrict__ Wl) {
    int s = blockIdx.x;            // 0..17
    int l = s / 6, j = s % 6;
    const float* src;
    switch (j) {
        case 0:  src = mlp_W1 + (size_t)l * 257 * 128; break;
        case 1:  src = mlp_W1 + (size_t)l * 257 * 128 + 128 * 128; break;
        case 2:  src = mlp_W2 + (size_t)l * 128 * 128; break;
        case 3:  src = upd_W1 + (size_t)l * 256 * 128; break;
        case 4:  src = upd_W1 + (size_t)l * 256 * 128 + 128 * 128; break;
        default: src = upd_W2 + (size_t)l * 128 * 128; break;
    }
    uint4* dh = reinterpret_cast<uint4*>(Wh + (size_t)s * 16384);
    uint4* dl = reinterpret_cast<uint4*>(Wl + (size_t)s * 16384);
    for (int c = threadIdx.x; c < 2048; c += blockDim.x) {
        int out = c >> 4, k0 = (c & 15) * 8;
        uint32_t hv[4], lv[4];
#pragma unroll
        for (int u = 0; u < 4; ++u) {
            float a = src[(size_t)(k0 + 2 * u) * 128 + out];
            float b = src[(size_t)(k0 + 2 * u + 1) * 128 + out];
            hv[u] = split_pair(a, b, lv[u]);
        }
        dh[c] = make_uint4(hv[0], hv[1], hv[2], hv[3]);
        dl[c] = make_uint4(lv[0], lv[1], lv[2], lv[3]);
    }
}

// ---------------- V = W2 @ U1b, vb = b2 @ U1b (fp32, then split) -------------
__global__ void prep_V(const float* __restrict__ mlp_W2, const float* __restrict__ mlp_b2,
                       const float* __restrict__ upd_W1,
                       __nv_bfloat16* __restrict__ Vh, __nv_bfloat16* __restrict__ Vl,
                       float* __restrict__ vb) {
    extern __shared__ float s[];
    float* Us = s;            // 16384
    float* Vs = s + 16384;    // 16384
    int l = blockIdx.x;
    int tid = threadIdx.x;
    const float* W2  = mlp_W2 + (size_t)l * 16384;
    const float* U1b = upd_W1 + (size_t)l * 256 * 128 + 128 * 128;
    const float* b2  = mlp_b2 + (size_t)l * 128;
    for (int i = tid; i < 16384; i += 256) Us[i] = U1b[i];
    __syncthreads();
    for (int idx = tid; idx < 16384; idx += 256) {
        int k = idx >> 7, j = idx & 127;
        float acc = 0.0f;
        const float* wr = W2 + k * 128;
#pragma unroll 8
        for (int m = 0; m < 128; ++m) acc = fmaf(wr[m], Us[m * 128 + j], acc);
        Vs[idx] = acc;
    }
    if (tid < 128) {
        float a = 0.0f;
#pragma unroll 8
        for (int k = 0; k < 128; ++k) a = fmaf(b2[k], Us[k * 128 + tid], a);
        vb[l * 128 + tid] = a;
    }
    __syncthreads();
    uint4* dh = reinterpret_cast<uint4*>(Vh + (size_t)l * 16384);
    uint4* dl = reinterpret_cast<uint4*>(Vl + (size_t)l * 16384);
    for (int c = tid; c < 2048; c += 256) {
        int out = c >> 4, k0 = (c & 15) * 8;
        uint32_t hv[4], lv[4];
#pragma unroll
        for (int u = 0; u < 4; ++u) {
            float a = Vs[(k0 + 2 * u) * 128 + out];
            float b = Vs[(k0 + 2 * u + 1) * 128 + out];
            hv[u] = split_pair(a, b, lv[u]);
        }
        dh[c] = make_uint4(hv[0], hv[1], hv[2], hv[3]);
        dl[c] = make_uint4(lv[0], lv[1], lv[2], lv[3]);
    }
}

// ---------------- fused message-pair GEMM: C0=x@W1a+b1, C1=x@W1b -------------
__global__ __launch_bounds__(256) void mma_gemm_msg(
    const float* __restrict__ X,
    const __nv_bfloat16* __restrict__ B0h, const __nv_bfloat16* __restrict__ B0l,
    const __nv_bfloat16* __restrict__ B1h, const __nv_bfloat16* __restrict__ B1l,
    const float* __restrict__ bias0,
    float* __restrict__ C0, float* __restrict__ C1, int M)
{
    extern __shared__ char sm[];
    char* Ah = sm;
    char* Al = sm + TILE_BYTES;
    char* Bh = sm + 2 * TILE_BYTES;
    char* Bl = sm + 3 * TILE_BYTES;
    const uint32_t sAh = smem_to_u32(Ah), sAl = smem_to_u32(Al);
    const uint32_t sBh = smem_to_u32(Bh), sBl = smem_to_u32(Bl);

    const int tid  = threadIdx.x;
    const int wid  = tid >> 5;
    const int lane = tid & 31;
    const int warp_m = wid & 3;
    const int warp_n = wid >> 2;
    const int m0 = blockIdx.x * 128;

    uint32_t a_off[2], b_off[4];
#pragma unroll
    for (int mt = 0; mt < 2; ++mt)
        a_off[mt] = (uint32_t)((warp_m * 32 + mt * 16 + (lane & 15)) * ROWB + (lane >> 4) * 16);
#pragma unroll
    for (int bt = 0; bt < 4; ++bt)
        b_off[bt] = (uint32_t)((warp_n * 64 + bt * 16 + ((lane >> 4) & 1) * 8 + (lane & 7)) * ROWB
                               + ((lane >> 3) & 1) * 16);

    fill_A_tiles(Ah, Al, X, m0, M, tid);

#pragma unroll 1
    for (int j = 0; j < 2; ++j) {
        if (j) __syncthreads();   // previous MMA reads done before B refill
        fill_B_tiles(Bh, Bl,
                     reinterpret_cast<const uint4*>(j ? B1h : B0h),
                     reinterpret_cast<const uint4*>(j ? B1l : B0l), tid);
        __syncthreads();

        float acc[2][8][4];
        zero_acc(acc);
        mma_3pass(acc, sAh, sAl, sBh, sBl, a_off, b_off);

        float* C = j ? C1 : C0;
        const float* bias = j ? nullptr : bias0;
#pragma unroll
        for (int mt = 0; mt < 2; ++mt) {
            int r0 = m0 + warp_m * 32 + mt * 16 + (lane >> 2);
#pragma unroll
            for (int half = 0; half < 2; ++half) {
                int r = r0 + half * 8;
                if (r >= M) continue;
#pragma unroll
                for (int nt = 0; nt < 8; ++nt) {
                    int col = warp_n * 64 + nt * 8 + (lane & 3) * 2;
                    float v0 = acc[mt][nt][2 * half + 0];
                    float v1 = acc[mt][nt][2 * half + 1];
                    if (bias != nullptr) { v0 += bias[col]; v1 += bias[col + 1]; }
                    *reinterpret_cast<float2*>(C + (size_t)r * HID + col) = make_float2(v0, v1);
                }
            }
        }
    }
}

// ---------------- fused update layer -----------------------------------------
// h = relu(X@U1a + S@V + ub1 + mask*vb); x_new = h@U2 + ub2; Xout = relu(LN(x_new))
__global__ __launch_bounds__(256) void update_fused(
    const float* __restrict__ X,
    const __nv_bfloat16* __restrict__ U1ah, const __nv_bfloat16* __restrict__ U1al,
    const float* __restrict__ S,
    const __nv_bfloat16* __restrict__ Vh, const __nv_bfloat16* __restrict__ Vl,
    const float* __restrict__ mask,
    const float* __restrict__ ub1, const float* __restrict__ vb,
    const __nv_bfloat16* __restrict__ U2h, const __nv_bfloat16* __restrict__ U2l,
    const float* __restrict__ ub2,
    const float* __restrict__ lng, const float* __restrict__ lnb,
    float* __restrict__ Xout, int M)
{
    extern __shared__ char sm[];
    char* Ah = sm;
    char* Al = sm + TILE_BYTES;
    char* Bh = sm + 2 * TILE_BYTES;
    char* Bl = sm + 3 * TILE_BYTES;
    float* stage = reinterpret_cast<float*>(Bh);   // reused AFTER stage-2 MMA
    const uint32_t sAh = smem_to_u32(Ah), sAl = smem_to_u32(Al);
    const uint32_t sBh = smem_to_u32(Bh), sBl = smem_to_u32(Bl);

    const int tid  = threadIdx.x;
    const int wid  = tid >> 5;
    const int lane = tid & 31;
    const int warp_m = wid & 3;
    const int warp_n = wid >> 2;
    const int m0 = blockIdx.x * 128;

    uint32_t a_off[2], b_off[4];
#pragma unroll
    for (int mt = 0; mt < 2; ++mt)
        a_off[mt] = (uint32_t)((warp_m * 32 + mt * 16 + (lane & 15)) * ROWB + (lane >> 4) * 16);
#pragma unroll
    for (int bt = 0; bt < 4; ++bt)
        b_off[bt] = (uint32_t)((warp_n * 64 + bt * 16 + ((lane >> 4) & 1) * 8 + (lane & 7)) * ROWB
                               + ((lane >> 3) & 1) * 16);

    // ---- stage 1: acc = X@U1a + S@V ----
    float acc[2][8][4];
    zero_acc(acc);
#pragma unroll 1
    for (int s = 0; s < 2; ++s) {
        if (s) __syncthreads();
        fill_A_tiles(Ah, Al, s ? S : X, m0, M, tid);
        fill_B_tiles(Bh, Bl,
                     reinterpret_cast<const uint4*>(s ? Vh : U1ah),
                     reinterpret_cast<const uint4*>(s ? Vl : U1al), tid);
        __syncthreads();
        mma_3pass(acc, sAh, sAl, sBh, sBl, a_off, b_off);
    }

    // ---- h = relu(acc + ub1 + mask*vb) -> write split bf16 back into A tiles ----
    __syncthreads();   // all warps done reading A tiles
#pragma unroll
    for (int mt = 0; mt < 2; ++mt) {
#pragma unroll
        for (int half = 0; half < 2; ++half) {
            int lr = warp_m * 32 + mt * 16 + (lane >> 2) + half * 8;
            int r = m0 + lr;
            float mk = (r < M) ? mask[r] : 0.0f;
#pragma unroll
            for (int nt = 0; nt < 8; ++nt) {
                int col = warp_n * 64 + nt * 8 + (lane & 3) * 2;
                float v0 = fmaxf(acc[mt][nt][2 * half + 0] + ub1[col + 0] + mk * vb[col + 0], 0.0f);
                float v1 = fmaxf(acc[mt][nt][2 * half + 1] + ub1[col + 1] + mk * vb[col + 1], 0.0f);
                uint32_t lo;
                uint32_t hi = split_pair(v0, v1, lo);
                uint32_t off = (uint32_t)(lr * ROWB + col * 2);
                *reinterpret_cast<uint32_t*>(Ah + off) = hi;
                *reinterpret_cast<uint32_t*>(Al + off) = lo;
            }
        }
    }
    // ---- stage 2: x_new = h@U2 ----
    fill_B_tiles(Bh, Bl, reinterpret_cast<const uint4*>(U2h),
                 reinterpret_cast<const uint4*>(U2l), tid);
    __syncthreads();
    zero_acc(acc);
    mma_3pass(acc, sAh, sAl, sBh, sBl, a_off, b_off);

    // ---- epilogue: + ub2, stage fp32 rows into smem ----
    __syncthreads();   // all warps done reading B tiles (stage aliases Bh)
#pragma unroll
    for (int mt = 0; mt < 2; ++mt) {
#pragma unroll
        for (int half = 0; half < 2; ++half) {
            int lr = warp_m * 32 + mt * 16 + (lane >> 2) + half * 8;
#pragma unroll
            for (int nt = 0; nt < 8; ++nt) {
                int col = warp_n * 64 + nt * 8 + (lane & 3) * 2;
                *reinterpret_cast<float2*>(stage + lr * STAGE_STRIDE + col) =
                    make_float2(acc[mt][nt][2 * half + 0] + ub2[col + 0],
                                acc[mt][nt][2 * half + 1] + ub2[col + 1]);
            }
        }
    }
    __syncthreads();

    // ---- LN + relu from staging, write Xout ----
#pragma unroll 1
    for (int i = 0; i < 16; ++i) {
        int lr = wid * 16 + i;
        int r = m0 + lr;
        if (r >= M) break;
        float4 v = *reinterpret_cast<const float4*>(stage + lr * STAGE_STRIDE + lane * 4);
        float s = v.x + v.y + v.z + v.w;
#pragma unroll
        for (int o = 16; o > 0; o >>= 1) s += __shfl_xor_sync(0xffffffffu, s, o);
        float mu = s * (1.0f / 128.0f);
        float dx = v.x - mu, dy = v.y - mu, dz = v.z - mu, dw = v.w - mu;
        float q = dx * dx + dy * dy + dz * dz + dw * dw;
#pragma unroll
        for (int o = 16; o > 0; o >>= 1) q += __shfl_xor_sync(0xffffffffu, q, o);
        float rsd = rsqrtf(q * (1.0f / 128.0f) + 1e-5f);
        float4 gg = *reinterpret_cast<const float4*>(lng + lane * 4);
        float4 bb = *reinterpret_cast<const float4*>(lnb + lane * 4);
        float4 rr;
        rr.x = fmaxf(fmaf(dx * rsd, gg.x, bb.x), 0.0f);
        rr.y = fmaxf(fmaf(dy * rsd, gg.y, bb.y), 0.0f);
        rr.z = fmaxf(fmaf(dz * rsd, gg.z, bb.z), 0.0f);
        rr.w = fmaxf(fmaf(dw * rsd, gg.w, bb.w), 0.0f);
        *reinterpret_cast<float4*>(Xout + (size_t)r * HID + lane * 4) = rr;
    }
}

// ---------------- CSR aggregation (writes inv-scaled sum) --------------------
__global__ __launch_bounds__(256) void agg_kernel(
    const float* __restrict__ A, const float* __restrict__ B,
    const int* __restrict__ srcs, const float* __restrict__ eas,
    const int* __restrict__ off, const float* __restrict__ cvec,
    const float* __restrict__ inv,
    float* __restrict__ S, int N)
{
    int node = (blockIdx.x * blockDim.x + threadIdx.x) >> 5;
    if (node >= N) return;
    int lane = threadIdx.x & 31;
    const float4 a = *reinterpret_cast<const float4*>(A + (size_t)node * HID + lane * 4);
    const float4 c = *reinterpret_cast<const float4*>(cvec + lane * 4);
    float4 s = make_float4(0.f, 0.f, 0.f, 0.f);
    int p  = off[node];
    int pe = off[node + 1];
    for (; p + 1 < pe; p += 2) {
        int s0 = srcs[p], s1 = srcs[p + 1];
        float e0 = eas[p], e1 = eas[p + 1];
        const float4 b0 = *reinterpret_cast<const float4*>(B + (size_t)s0 * HID + lane * 4);
        const float4 b1 = *reinterpret_cast<const float4*>(B + (size_t)s1 * HID + lane * 4);
        s.x += fmaxf(fmaf(e0, c.x, a.x + b0.x), 0.0f) + fmaxf(fmaf(e1, c.x, a.x + b1.x), 0.0f);
        s.y += fmaxf(fmaf(e0, c.y, a.y + b0.y), 0.0f) + fmaxf(fmaf(e1, c.y, a.y + b1.y), 0.0f);
        s.z += fmaxf(fmaf(e0, c.z, a.z + b0.z), 0.0f) + fmaxf(fmaf(e1, c.z, a.z + b1.z), 0.0f);
        s.w += fmaxf(fmaf(e0, c.w, a.w + b0.w), 0.0f) + fmaxf(fmaf(e1, c.w, a.w + b1.w), 0.0f);
    }
    if (p < pe) {
        int s0 = srcs[p];
        float e0 = eas[p];
        const float4 b0 = *reinterpret_cast<const float4*>(B + (size_t)s0 * HID + lane * 4);
        s.x += fmaxf(fmaf(e0, c.x, a.x + b0.x), 0.0f);
        s.y += fmaxf(fmaf(e0, c.y, a.y + b0.y), 0.0f);
        s.z += fmaxf(fmaf(e0, c.z, a.z + b0.z), 0.0f);
        s.w += fmaxf(fmaf(e0, c.w, a.w + b0.w), 0.0f);
    }
    float iv = inv[node];
    s.x *= iv; s.y *= iv; s.z *= iv; s.w *= iv;
    *reinterpret_cast<float4*>(S + (size_t)node * HID + lane * 4) = s;
}

// ---------------- column sum + head ------------------------------------------
__global__ void colsum_kernel(const float* __restrict__ x, float* __restrict__ cs, int N) {
    int col = threadIdx.x & 127;
    int rg  = threadIdx.x >> 7;
    float s = 0.0f;
    for (int row = blockIdx.x * 2 + rg; row < N; row += gridDim.x * 2)
        s += x[(size_t)row * HID + col];
    atomicAdd(&cs[col], s);
}
__global__ void head_kernel(const float* __restrict__ cs,
                            const float* __restrict__ W1, const float* __restrict__ b1,
                            const float* __restrict__ W2, const float* __restrict__ b2,
                            float* __restrict__ out, float invN)
{
    __shared__ float g[HID], h[HID];
    int t = threadIdx.x;
    g[t] = cs[t] * invN;
    __syncthreads();
    float acc = b1[t];
#pragma unroll 8
    for (int k = 0; k < HID; ++k) acc = fmaf(g[k], W1[k * HID + t], acc);
    h[t] = fmaxf(acc, 0.0f);
    __syncthreads();
    float o = b2[t];
#pragma unroll 8
    for (int k = 0; k < HID; ++k) o = fmaf(h[k], W2[k * HID + t], o);
    out[t] = o;
}

// ---------------- launch ----------------------------------------------------
extern "C" void kernel_launch(void* const* d_in, const int* in_sizes, int n_in,
                              void* d_out, int out_size) {
    const float* node_feat = (const float*)d_in[0];
    const float* edge_attr = (const float*)d_in[1];
    const float* enc_W     = (const float*)d_in[2];
    const float* enc_b     = (const float*)d_in[3];
    const float* mlp_W1    = (const float*)d_in[4];
    const float* mlp_b1    = (const float*)d_in[5];
    const float* mlp_W2    = (const float*)d_in[6];
    const float* mlp_b2    = (const float*)d_in[7];
    const float* upd_W1    = (const float*)d_in[8];
    const float* upd_b1    = (const float*)d_in[9];
    const float* upd_W2    = (const float*)d_in[10];
    const float* upd_b2    = (const float*)d_in[11];
    const float* ln_g      = (const float*)d_in[12];
    const float* ln_b      = (const float*)d_in[13];
    const float* out_W1    = (const float*)d_in[14];
    const float* out_b1    = (const float*)d_in[15];
    const float* out_W2    = (const float*)d_in[16];
    const float* out_b2    = (const float*)d_in[17];
    const void*  edge_idx  = d_in[18];

    const int N = in_sizes[0] / 5;
    const int E = in_sizes[18] / 2;

    float *px, *pA, *pB, *pS, *pinv, *pmask, *pcs, *peas, *pvb;
    int *pflag, *pcnt, *poff, *pcur, *pbsum, *psrcs;
    __nv_bfloat16 *pWh, *pWl, *pVh, *pVl;
    cudaGetSymbolAddress((void**)&px,    g_x);
    cudaGetSymbolAddress((void**)&pA,    g_A);
    cudaGetSymbolAddress((void**)&pB,    g_B);
    cudaGetSymbolAddress((void**)&pS,    g_S);
    cudaGetSymbolAddress((void**)&pinv,  g_inv);
    cudaGetSymbolAddress((void**)&pmask, g_mask);
    cudaGetSymbolAddress((void**)&pcs,   g_colsum);
    cudaGetSymbolAddress((void**)&pflag, g_is64);
    cudaGetSymbolAddress((void**)&pcnt,  g_cnt);
    cudaGetSymbolAddress((void**)&poff,  g_off);
    cudaGetSymbolAddress((void**)&pcur,  g_cur);
    cudaGetSymbolAddress((void**)&pbsum, g_bsum);
    cudaGetSymbolAddress((void**)&psrcs, g_srcs);
    cudaGetSymbolAddress((void**)&peas,  g_eas);
    cudaGetSymbolAddress((void**)&pWh,   g_Wh);
    cudaGetSymbolAddress((void**)&pWl,   g_Wl);
    cudaGetSymbolAddress((void**)&pVh,   g_Vh);
    cudaGetSymbolAddress((void**)&pVl,   g_Vl);
    cudaGetSymbolAddress((void**)&pvb,   g_vb);

    cudaFuncSetAttribute(mma_gemm_msg, cudaFuncAttributeMaxDynamicSharedMemorySize, DSMEM_SZ);
    cudaFuncSetAttribute(update_fused, cudaFuncAttributeMaxDynamicSharedMemorySize, DSMEM_SZ);
    cudaFuncSetAttribute(prep_V,       cudaFuncAttributeMaxDynamicSharedMemorySize, 131072);

    const int gemm_grid = (N + 127) / 128;
    const int scan_blocks = (N + 1023) / 1024;

    // order: slot 5 (ncu -s 5 -c 1) = first mma_gemm_msg (the GEMM engine)
    detect_idx_kernel<<<1, 1>>>(edge_idx, E, pflag);                               // 0
    prep_weights<<<18, 256>>>(mlp_W1, mlp_W2, upd_W1, upd_W2, pWh, pWl);           // 1
    prep_V<<<3, 256, 131072>>>(mlp_W2, mlp_b2, upd_W1, pVh, pVl, pvb);             // 2
    cudaMemsetAsync(pcnt, 0, (size_t)N * sizeof(int));                             // 3
    encoder_kernel<<<(N * HID + 255) / 256, 256>>>(node_feat, enc_W, enc_b, px, N);// 4
    mma_gemm_msg<<<gemm_grid, 256, DSMEM_SZ>>>(px,                                 // 5
        pWh + 0 * 16384, pWl + 0 * 16384, pWh + 1 * 16384, pWl + 1 * 16384,
        mlp_b1, pA, pB, N);
    hist_kernel<<<(E + 255) / 256, 256>>>(edge_idx, pflag, pcnt, E);
    scan1_kernel<<<scan_blocks, 1024>>>(pcnt, poff, pbsum, N);
    scan2_kernel<<<1, 64>>>(pbsum, scan_blocks);
    scan3_kernel<<<(N + 255) / 256, 256>>>(poff, pcur, pbsum, pcnt, pinv, pmask, N, E);
    scatter_kernel<<<(E + 255) / 256, 256>>>(edge_idx, pflag, edge_attr, pcur, psrcs, peas, E);

    for (int l = 0; l < 3; ++l) {
        const float* cve = mlp_W1 + (size_t)l * 257 * HID + 256 * HID;
        const float* ub1 = upd_b1 + (size_t)l * HID;
        const float* ub2 = upd_b2 + (size_t)l * HID;
        __nv_bfloat16* U1a_h = pWh + (size_t)(l * 6 + 3) * 16384;
        __nv_bfloat16* U1a_l = pWl + (size_t)(l * 6 + 3) * 16384;
        __nv_bfloat16* U2_h  = pWh + (size_t)(l * 6 + 5) * 16384;
        __nv_bfloat16* U2_l  = pWl + (size_t)(l * 6 + 5) * 16384;

        // S[i] = inv[i] * sum over CSR adj of relu(A[i]+B[src]+ea*c)
        agg_kernel<<<(N * 32 + 255) / 256, 256>>>(pA, pB, psrcs, peas, poff, cve, pinv, pS, N);

        // x = relu(LN(relu(x@U1a + S@V + ub1 + mask*vb)@U2 + ub2))
        update_fused<<<gemm_grid, 256, DSMEM_SZ>>>(px, U1a_h, U1a_l, pS,
            pVh + (size_t)l * 16384, pVl + (size_t)l * 16384, pmask,
            ub1, pvb + (size_t)l * HID, U2_h, U2_l, ub2,
            ln_g + (size_t)l * HID, ln_b + (size_t)l * HID, px, N);

        // next layer's message GEMMs
        if (l < 2) {
            const int ln = l + 1;
            mma_gemm_msg<<<gemm_grid, 256, DSMEM_SZ>>>(px,
                pWh + (size_t)(ln * 6 + 0) * 16384, pWl + (size_t)(ln * 6 + 0) * 16384,
                pWh + (size_t)(ln * 6 + 1) * 16384, pWl + (size_t)(ln * 6 + 1) * 16384,
                mlp_b1 + (size_t)ln * HID, pA, pB, N);
        }
    }

    cudaMemsetAsync(pcs, 0, HID * sizeof(float));
    colsum_kernel<<<128, 256>>>(px, pcs, N);
    head_kernel<<<1, HID>>>(pcs, out_W1, out_b1, out_W2, out_b2,
                            (float*)d_out, 1.0f / (float)N);
}

// round 14
// speedup vs baseline: 1.1712x; 1.1611x over previous
#include <cuda_runtime.h>
#include <cuda_bf16.h>
#include <cstdint>

#define NNODES 50000
#define NEDGES 800000
#define HID    128

// ---------------- scratch (device globals; no allocation allowed) ----------
__device__ float g_x[NNODES * HID];
__device__ float g_A[NNODES * HID];
__device__ float g_B[NNODES * HID];
__device__ float g_S[NNODES * HID];
__device__ float g_T[NNODES * HID];
__device__ float g_inv[NNODES];
__device__ float g_mask[NNODES];
__device__ float g_colsum[HID];
__device__ int   g_is64;
// CSR by dst
__device__ int   g_cnt[NNODES];
__device__ int   g_off[NNODES + 1];
__device__ int   g_cur[NNODES];
__device__ int   g_bsum[64];
__device__ int   g_srcs[NEDGES];
__device__ float g_eas[NEDGES];
// 18 weight slices (3 layers x {W1a,W1b,W2,U1a,U1b,U2}), each 128x128 bf16,
// transposed ([out][k], packed row-major), hi and lo parts.
__device__ __nv_bfloat16 g_Wh[18 * 16384];
__device__ __nv_bfloat16 g_Wl[18 * 16384];

// ---------------- helpers ----------------------------------------------------
__device__ __forceinline__ uint32_t smem_to_u32(const void* smem_ptr) {
    uint32_t addr;
    asm("{ .reg .u64 tmp; cvta.to.shared.u64 tmp, %1; cvt.u32.u64 %0, tmp; }"
        : "=r"(addr) : "l"(smem_ptr));
    return addr;
}
__device__ __forceinline__ uint32_t split_pair(float a, float b, uint32_t& lo) {
    __nv_bfloat16 ha = __float2bfloat16(a), hb = __float2bfloat16(b);
    __nv_bfloat16 la = __float2bfloat16(a - __bfloat162float(ha));
    __nv_bfloat16 lb = __float2bfloat16(b - __bfloat162float(hb));
    lo = (uint32_t)__bfloat16_as_ushort(la) | ((uint32_t)__bfloat16_as_ushort(lb) << 16);
    return (uint32_t)__bfloat16_as_ushort(ha) | ((uint32_t)__bfloat16_as_ushort(hb) << 16);
}
__device__ __forceinline__ void ldmatrix_x4(uint32_t& r0, uint32_t& r1,
                                            uint32_t& r2, uint32_t& r3, uint32_t addr) {
    asm volatile("ldmatrix.sync.aligned.m8n8.x4.shared.b16 {%0,%1,%2,%3}, [%4];"
                 : "=r"(r0), "=r"(r1), "=r"(r2), "=r"(r3) : "r"(addr));
}
__device__ __forceinline__ void mma16816(float* d, const uint32_t* a, const uint32_t* b) {
    asm volatile(
        "mma.sync.aligned.m16n8k16.row.col.f32.bf16.bf16.f32 "
        "{%0,%1,%2,%3}, {%4,%5,%6,%7}, {%8,%9}, {%0,%1,%2,%3};"
        : "+f"(d[0]), "+f"(d[1]), "+f"(d[2]), "+f"(d[3])
        : "r"(a[0]), "r"(a[1]), "r"(a[2]), "r"(a[3]), "r"(b[0]), "r"(b[1]));
}

#define ROWB 272
#define TILE_BYTES (128 * ROWB)   // 34816
#define DSMEM_SZ (4 * TILE_BYTES) // 139264
#define STAGE_STRIDE 132          // fp32 staging row stride (words)

// ---- common fill helpers -----------------------------------------------------
__device__ __forceinline__ void fill_B_tiles(char* Bh, char* Bl,
                                             const uint4* gBh, const uint4* gBl, int tid) {
#pragma unroll
    for (int i = 0; i < 8; ++i) {
        int cidx = tid + i * 256;
        int row = cidx >> 4, c = cidx & 15;
        uint32_t off = (uint32_t)(row * ROWB + c * 16);
        *reinterpret_cast<uint4*>(Bh + off) = gBh[cidx];
        *reinterpret_cast<uint4*>(Bl + off) = gBl[cidx];
    }
}
__device__ __forceinline__ void fill_A_tiles(char* Ah, char* Al, const float* A,
                                             const float* rowscale, int m0, int M, int tid) {
#pragma unroll
    for (int i = 0; i < 8; ++i) {
        int cidx = tid + i * 256;
        int row = cidx >> 4, c = cidx & 15;
        int arow = m0 + row;
        int k0 = c * 8;
        uint32_t off = (uint32_t)(row * ROWB + c * 16);
        uint4 hv4 = make_uint4(0u, 0u, 0u, 0u), lv4 = make_uint4(0u, 0u, 0u, 0u);
        if (arow < M) {
            float4 v0 = *reinterpret_cast<const float4*>(A + (size_t)arow * HID + k0);
            float4 v1 = *reinterpret_cast<const float4*>(A + (size_t)arow * HID + k0 + 4);
            if (rowscale != nullptr) {
                float rs = rowscale[arow];
                v0.x *= rs; v0.y *= rs; v0.z *= rs; v0.w *= rs;
                v1.x *= rs; v1.y *= rs; v1.z *= rs; v1.w *= rs;
            }
            uint32_t lo;
            hv4.x = split_pair(v0.x, v0.y, lo); lv4.x = lo;
            hv4.y = split_pair(v0.z, v0.w, lo); lv4.y = lo;
            hv4.z = split_pair(v1.x, v1.y, lo); lv4.z = lo;
            hv4.w = split_pair(v1.z, v1.w, lo); lv4.w = lo;
        }
        *reinterpret_cast<uint4*>(Ah + off) = hv4;
        *reinterpret_cast<uint4*>(Al + off) = lv4;
    }
}
// 3-pass split MMA over current smem tiles into acc
__device__ __forceinline__ void mma_3pass(float acc[2][8][4],
                                          uint32_t sAh, uint32_t sAl,
                                          uint32_t sBh, uint32_t sBl,
                                          const uint32_t a_off[2], const uint32_t b_off[4]) {
    uint32_t pa[3] = { sAh, sAl, sAh };
    uint32_t pb[3] = { sBh, sBh, sBl };
#pragma unroll
    for (int p = 0; p < 3; ++p) {
        uint32_t abase = pa[p], bbase = pb[p];
#pragma unroll
        for (int kk = 0; kk < 8; ++kk) {
            uint32_t a[2][4];
            uint32_t b[8][2];
#pragma unroll
            for (int mt = 0; mt < 2; ++mt)
                ldmatrix_x4(a[mt][0], a[mt][1], a[mt][2], a[mt][3],
                            abase + a_off[mt] + kk * 32);
#pragma unroll
            for (int bt = 0; bt < 4; ++bt)
                ldmatrix_x4(b[2 * bt][0], b[2 * bt][1], b[2 * bt + 1][0], b[2 * bt + 1][1],
                            bbase + b_off[bt] + kk * 32);
#pragma unroll
            for (int mt = 0; mt < 2; ++mt)
#pragma unroll
                for (int nt = 0; nt < 8; ++nt)
                    mma16816(acc[mt][nt], a[mt], b[nt]);
        }
    }
}
__device__ __forceinline__ void zero_acc(float acc[2][8][4]) {
#pragma unroll
    for (int a = 0; a < 2; ++a)
#pragma unroll
        for (int b = 0; b < 8; ++b)
#pragma unroll
            for (int c = 0; c < 4; ++c) acc[a][b][c] = 0.0f;
}

// ---------------- index dtype detection ------------------------------------
__global__ void detect_idx_kernel(const void* idx, int E, int* flag) {
    const long long* p = (const long long*)idx;
    int is64 = 1;
    int n = (E < 128) ? E : 128;
    for (int i = 0; i < n; ++i) {
        long long v = p[i];
        if (v < 0 || v >= NNODES) { is64 = 0; break; }
    }
    *flag = is64;
}
__device__ __forceinline__ int load_idx(const void* idx, int is64, long long pos) {
    if (is64) return (int)((const long long*)idx)[pos];
    return ((const int*)idx)[pos];
}

// ---------------- CSR build --------------------------------------------------
__global__ void hist_kernel(const void* __restrict__ idx, const int* __restrict__ flag,
                            int* __restrict__ cnt, int E) {
    int e = blockIdx.x * blockDim.x + threadIdx.x;
    if (e >= E) return;
    int dst = load_idx(idx, *flag, (long long)E + e);
    atomicAdd(&cnt[dst], 1);
}
__global__ void scan1_kernel(const int* __restrict__ cnt, int* __restrict__ off,
                             int* __restrict__ bsum, int N) {
    __shared__ int sm[1024];
    int i = blockIdx.x * 1024 + threadIdx.x;
    int v = (i < N) ? cnt[i] : 0;
    sm[threadIdx.x] = v;
    __syncthreads();
#pragma unroll
    for (int o = 1; o < 1024; o <<= 1) {
        int t = (threadIdx.x >= o) ? sm[threadIdx.x - o] : 0;
        __syncthreads();
        sm[threadIdx.x] += t;
        __syncthreads();
    }
    if (i < N) off[i] = sm[threadIdx.x] - v;   // exclusive
    if (threadIdx.x == 1023) bsum[blockIdx.x] = sm[1023];
}
__global__ void scan2_kernel(int* bsum, int nb) {
    __shared__ int sm[64];
    int t = threadIdx.x;
    int v = (t < nb) ? bsum[t] : 0;
    sm[t] = v;
    __syncthreads();
#pragma unroll
    for (int o = 1; o < 64; o <<= 1) {
        int u = (t >= o) ? sm[t - o] : 0;
        __syncthreads();
        sm[t] += u;
        __syncthreads();
    }
    if (t < nb) bsum[t] = sm[t] - v;   // exclusive
}
__global__ void scan3_kernel(int* __restrict__ off, int* __restrict__ cur,
                             const int* __restrict__ bsum,
                             const int* __restrict__ cnt,
                             float* __restrict__ inv, float* __restrict__ mask,
                             int N, int E) {
    int i = blockIdx.x * blockDim.x + threadIdx.x;
    if (i == 0) off[N] = E;
    if (i >= N) return;
    int o = off[i] + bsum[i >> 10];
    off[i] = o;
    cur[i] = o;
    int c = cnt[i];
    inv[i]  = 1.0f / (float)((c > 1) ? c : 1);
    mask[i] = (c > 0) ? 1.0f : 0.0f;
}
__global__ void scatter_kernel(const void* __restrict__ idx, const int* __restrict__ flag,
                               const float* __restrict__ eattr,
                               int* __restrict__ cur, int* __restrict__ srcs,
                               float* __restrict__ eas, int E) {
    int e = blockIdx.x * blockDim.x + threadIdx.x;
    if (e >= E) return;
    int is64 = *flag;
    int src = load_idx(idx, is64, e);
    int dst = load_idx(idx, is64, (long long)E + e);
    int p = atomicAdd(&cur[dst], 1);
    srcs[p] = src;
    eas[p]  = eattr[e];
}

// ---------------- encoder ----------------------------------------------------
__global__ void encoder_kernel(const float* __restrict__ nf, const float* __restrict__ W,
                               const float* __restrict__ b, float* __restrict__ x, int N) {
    int i = blockIdx.x * blockDim.x + threadIdx.x;
    if (i >= N * HID) return;
    int n = i >> 7;
    int h = i & 127;
    float acc = b[h];
#pragma unroll
    for (int k = 0; k < 5; ++k)
        acc = fmaf(nf[n * 5 + k], W[k * HID + h], acc);
    x[i] = acc;
}

// ---------------- weight prep ------------------------------------------------
__global__ void prep_weights(const float* __restrict__ mlp_W1, const float* __restrict__ mlp_W2,
                             const float* __restrict__ upd_W1, const float* __restrict__ upd_W2,
                             __nv_bfloat16* __restrict__ Wh, __nv_bfloat16* __restrict__ Wl) {
    int s = blockIdx.x;            // 0..17
    int l = s / 6, j = s % 6;
    const float* src;
    switch (j) {
        case 0:  src = mlp_W1 + (size_t)l * 257 * 128; break;
        case 1:  src = mlp_W1 + (size_t)l * 257 * 128 + 128 * 128; break;
        case 2:  src = mlp_W2 + (size_t)l * 128 * 128; break;
        case 3:  src = upd_W1 + (size_t)l * 256 * 128; break;
        case 4:  src = upd_W1 + (size_t)l * 256 * 128 + 128 * 128; break;
        default: src = upd_W2 + (size_t)l * 128 * 128; break;
    }
    uint4* dh = reinterpret_cast<uint4*>(Wh + (size_t)s * 16384);
    uint4* dl = reinterpret_cast<uint4*>(Wl + (size_t)s * 16384);
    for (int c = threadIdx.x; c < 2048; c += blockDim.x) {
        int out = c >> 4, k0 = (c & 15) * 8;
        uint32_t hv[4], lv[4];
#pragma unroll
        for (int u = 0; u < 4; ++u) {
            float a = src[(size_t)(k0 + 2 * u) * 128 + out];
            float b = src[(size_t)(k0 + 2 * u + 1) * 128 + out];
            hv[u] = split_pair(a, b, lv[u]);
        }
        dh[c] = make_uint4(hv[0], hv[1], hv[2], hv[3]);
        dl[c] = make_uint4(lv[0], lv[1], lv[2], lv[3]);
    }
}

// ---------------- generic single-slice GEMM (for S@W2) -----------------------
__global__ __launch_bounds__(256) void mma_gemm(
    const float* __restrict__ A0,
    const __nv_bfloat16* __restrict__ B0h, const __nv_bfloat16* __restrict__ B0l,
    const float* __restrict__ bias, const float* __restrict__ rowscale,
    const float* __restrict__ biasmask,
    float* __restrict__ C, int M)
{
    extern __shared__ char sm[];
    char* Ah = sm;
    char* Al = sm + TILE_BYTES;
    char* Bh = sm + 2 * TILE_BYTES;
    char* Bl = sm + 3 * TILE_BYTES;
    const uint32_t sAh = smem_to_u32(Ah), sAl = smem_to_u32(Al);
    const uint32_t sBh = smem_to_u32(Bh), sBl = smem_to_u32(Bl);

    const int tid  = threadIdx.x;
    const int wid  = tid >> 5;
    const int lane = tid & 31;
    const int warp_m = wid & 3;
    const int warp_n = wid >> 2;
    const int m0 = blockIdx.x * 128;

    float acc[2][8][4];
    zero_acc(acc);

    uint32_t a_off[2], b_off[4];
#pragma unroll
    for (int mt = 0; mt < 2; ++mt)
        a_off[mt] = (uint32_t)((warp_m * 32 + mt * 16 + (lane & 15)) * ROWB + (lane >> 4) * 16);
#pragma unroll
    for (int bt = 0; bt < 4; ++bt)
        b_off[bt] = (uint32_t)((warp_n * 64 + bt * 16 + ((lane >> 4) & 1) * 8 + (lane & 7)) * ROWB
                               + ((lane >> 3) & 1) * 16);

    fill_B_tiles(Bh, Bl, reinterpret_cast<const uint4*>(B0h),
                 reinterpret_cast<const uint4*>(B0l), tid);
    fill_A_tiles(Ah, Al, A0, rowscale, m0, M, tid);
    __syncthreads();
    mma_3pass(acc, sAh, sAl, sBh, sBl, a_off, b_off);

#pragma unroll
    for (int mt = 0; mt < 2; ++mt) {
        int r0 = m0 + warp_m * 32 + mt * 16 + (lane >> 2);
#pragma unroll
        for (int half = 0; half < 2; ++half) {
            int r = r0 + half * 8;
            if (r >= M) continue;
            float bm = (biasmask != nullptr) ? biasmask[r] : 1.0f;
#pragma unroll
            for (int nt = 0; nt < 8; ++nt) {
                int col = warp_n * 64 + nt * 8 + (lane & 3) * 2;
                float v0 = acc[mt][nt][2 * half + 0];
                float v1 = acc[mt][nt][2 * half + 1];
                if (bias != nullptr) {
                    v0 = fmaf(bm, bias[col + 0], v0);
                    v1 = fmaf(bm, bias[col + 1], v1);
                }
                *reinterpret_cast<float2*>(C + (size_t)r * HID + col) = make_float2(v0, v1);
            }
        }
    }
}

// ---------------- fused message-pair GEMM: C0=x@W1a+b1, C1=x@W1b -------------
__global__ __launch_bounds__(256) void mma_gemm_msg(
    const float* __restrict__ X,
    const __nv_bfloat16* __restrict__ B0h, const __nv_bfloat16* __restrict__ B0l,
    const __nv_bfloat16* __restrict__ B1h, const __nv_bfloat16* __restrict__ B1l,
    const float* __restrict__ bias0,
    float* __restrict__ C0, float* __restrict__ C1, int M)
{
    extern __shared__ char sm[];
    char* Ah = sm;
    char* Al = sm + TILE_BYTES;
    char* Bh = sm + 2 * TILE_BYTES;
    char* Bl = sm + 3 * TILE_BYTES;
    const uint32_t sAh = smem_to_u32(Ah), sAl = smem_to_u32(Al);
    const uint32_t sBh = smem_to_u32(Bh), sBl = smem_to_u32(Bl);

    const int tid  = threadIdx.x;
    const int wid  = tid >> 5;
    const int lane = tid & 31;
    const int warp_m = wid & 3;
    const int warp_n = wid >> 2;
    const int m0 = blockIdx.x * 128;

    uint32_t a_off[2], b_off[4];
#pragma unroll
    for (int mt = 0; mt < 2; ++mt)
        a_off[mt] = (uint32_t)((warp_m * 32 + mt * 16 + (lane & 15)) * ROWB + (lane >> 4) * 16);
#pragma unroll
    for (int bt = 0; bt < 4; ++bt)
        b_off[bt] = (uint32_t)((warp_n * 64 + bt * 16 + ((lane >> 4) & 1) * 8 + (lane & 7)) * ROWB
                               + ((lane >> 3) & 1) * 16);

    fill_A_tiles(Ah, Al, X, nullptr, m0, M, tid);

#pragma unroll 1
    for (int j = 0; j < 2; ++j) {
        if (j) __syncthreads();   // previous MMA reads done before B refill
        fill_B_tiles(Bh, Bl,
                     reinterpret_cast<const uint4*>(j ? B1h : B0h),
                     reinterpret_cast<const uint4*>(j ? B1l : B0l), tid);
        __syncthreads();

        float acc[2][8][4];
        zero_acc(acc);
        mma_3pass(acc, sAh, sAl, sBh, sBl, a_off, b_off);

        float* C = j ? C1 : C0;
        const float* bias = j ? nullptr : bias0;
#pragma unroll
        for (int mt = 0; mt < 2; ++mt) {
            int r0 = m0 + warp_m * 32 + mt * 16 + (lane >> 2);
#pragma unroll
            for (int half = 0; half < 2; ++half) {
                int r = r0 + half * 8;
                if (r >= M) continue;
#pragma unroll
                for (int nt = 0; nt < 8; ++nt) {
                    int col = warp_n * 64 + nt * 8 + (lane & 3) * 2;
                    float v0 = acc[mt][nt][2 * half + 0];
                    float v1 = acc[mt][nt][2 * half + 1];
                    if (bias != nullptr) { v0 += bias[col]; v1 += bias[col + 1]; }
                    *reinterpret_cast<float2*>(C + (size_t)r * HID + col) = make_float2(v0, v1);
                }
            }
        }
    }
}

// ---------------- fused update layer -----------------------------------------
// h = relu(X@U1a + T@U1b + ub1); x_new = h@U2 + ub2; X_out = relu(LN(x_new))
__global__ __launch_bounds__(256) void update_fused(
    const float* __restrict__ X,
    const __nv_bfloat16* __restrict__ U1ah, const __nv_bfloat16* __restrict__ U1al,
    const float* __restrict__ T,
    const __nv_bfloat16* __restrict__ U1bh, const __nv_bfloat16* __restrict__ U1bl,
    const float* __restrict__ ub1,
    const __nv_bfloat16* __restrict__ U2h, const __nv_bfloat16* __restrict__ U2l,
    const float* __restrict__ ub2,
    const float* __restrict__ lng, const float* __restrict__ lnb,
    float* __restrict__ Xout, int M)
{
    extern __shared__ char sm[];
    char* Ah = sm;
    char* Al = sm + TILE_BYTES;
    char* Bh = sm + 2 * TILE_BYTES;
    char* Bl = sm + 3 * TILE_BYTES;
    float* stage = reinterpret_cast<float*>(Bh);   // reused AFTER stage-2 MMA
    const uint32_t sAh = smem_to_u32(Ah), sAl = smem_to_u32(Al);
    const uint32_t sBh = smem_to_u32(Bh), sBl = smem_to_u32(Bl);

    const int tid  = threadIdx.x;
    const int wid  = tid >> 5;
    const int lane = tid & 31;
    const int warp_m = wid & 3;
    const int warp_n = wid >> 2;
    const int m0 = blockIdx.x * 128;

    uint32_t a_off[2], b_off[4];
#pragma unroll
    for (int mt = 0; mt < 2; ++mt)
        a_off[mt] = (uint32_t)((warp_m * 32 + mt * 16 + (lane & 15)) * ROWB + (lane >> 4) * 16);
#pragma unroll
    for (int bt = 0; bt < 4; ++bt)
        b_off[bt] = (uint32_t)((warp_n * 64 + bt * 16 + ((lane >> 4) & 1) * 8 + (lane & 7)) * ROWB
                               + ((lane >> 3) & 1) * 16);

    // ---- stage 1: acc = X@U1a + T@U1b ----
    float acc[2][8][4];
    zero_acc(acc);
#pragma unroll 1
    for (int s = 0; s < 2; ++s) {
        if (s) __syncthreads();
        fill_A_tiles(Ah, Al, s ? T : X, nullptr, m0, M, tid);
        fill_B_tiles(Bh, Bl,
                     reinterpret_cast<const uint4*>(s ? U1bh : U1ah),
                     reinterpret_cast<const uint4*>(s ? U1bl : U1al), tid);
        __syncthreads();
        mma_3pass(acc, sAh, sAl, sBh, sBl, a_off, b_off);
    }

    // ---- h = relu(acc + ub1) -> write split bf16 back into A tiles ----
    __syncthreads();   // all warps done reading A tiles
#pragma unroll
    for (int mt = 0; mt < 2; ++mt) {
#pragma unroll
        for (int half = 0; half < 2; ++half) {
            int lr = warp_m * 32 + mt * 16 + (lane >> 2) + half * 8;
#pragma unroll
            for (int nt = 0; nt < 8; ++nt) {
                int col = warp_n * 64 + nt * 8 + (lane & 3) * 2;
                float v0 = fmaxf(acc[mt][nt][2 * half + 0] + ub1[col + 0], 0.0f);
                float v1 = fmaxf(acc[mt][nt][2 * half + 1] + ub1[col + 1], 0.0f);
                uint32_t lo;
                uint32_t hi = split_pair(v0, v1, lo);
                uint32_t off = (uint32_t)(lr * ROWB + col * 2);
                *reinterpret_cast<uint32_t*>(Ah + off) = hi;
                *reinterpret_cast<uint32_t*>(Al + off) = lo;
            }
        }
    }
    // ---- stage 2: x_new = h@U2 ----
    fill_B_tiles(Bh, Bl, reinterpret_cast<const uint4*>(U2h),
                 reinterpret_cast<const uint4*>(U2l), tid);
    __syncthreads();
    zero_acc(acc);
    mma_3pass(acc, sAh, sAl, sBh, sBl, a_off, b_off);

    // ---- epilogue: + ub2, stage fp32 rows into smem ----
    __syncthreads();   // all warps done reading B tiles (stage aliases Bh)
#pragma unroll
    for (int mt = 0; mt < 2; ++mt) {
#pragma unroll
        for (int half = 0; half < 2; ++half) {
            int lr = warp_m * 32 + mt * 16 + (lane >> 2) + half * 8;
#pragma unroll
            for (int nt = 0; nt < 8; ++nt) {
                int col = warp_n * 64 + nt * 8 + (lane & 3) * 2;
                *reinterpret_cast<float2*>(stage + lr * STAGE_STRIDE + col) =
                    make_float2(acc[mt][nt][2 * half + 0] + ub2[col + 0],
                                acc[mt][nt][2 * half + 1] + ub2[col + 1]);
            }
        }
    }
    __syncthreads();

    // ---- LN + relu from staging, write Xout ----
#pragma unroll 1
    for (int i = 0; i < 16; ++i) {
        int lr = wid * 16 + i;
        int r = m0 + lr;
        if (r >= M) break;
        float4 v = *reinterpret_cast<const float4*>(stage + lr * STAGE_STRIDE + lane * 4);
        float s = v.x + v.y + v.z + v.w;
#pragma unroll
        for (int o = 16; o > 0; o >>= 1) s += __shfl_xor_sync(0xffffffffu, s, o);
        float mu = s * (1.0f / 128.0f);
        float dx = v.x - mu, dy = v.y - mu, dz = v.z - mu, dw = v.w - mu;
        float q = dx * dx + dy * dy + dz * dz + dw * dw;
#pragma unroll
        for (int o = 16; o > 0; o >>= 1) q += __shfl_xor_sync(0xffffffffu, q, o);
        float rsd = rsqrtf(q * (1.0f / 128.0f) + 1e-5f);
        float4 gg = *reinterpret_cast<const float4*>(lng + lane * 4);
        float4 bb = *reinterpret_cast<const float4*>(lnb + lane * 4);
        float4 rr;
        rr.x = fmaxf(fmaf(dx * rsd, gg.x, bb.x), 0.0f);
        rr.y = fmaxf(fmaf(dy * rsd, gg.y, bb.y), 0.0f);
        rr.z = fmaxf(fmaf(dz * rsd, gg.z, bb.z), 0.0f);
        rr.w = fmaxf(fmaf(dw * rsd, gg.w, bb.w), 0.0f);
        *reinterpret_cast<float4*>(Xout + (size_t)r * HID + lane * 4) = rr;
    }
}

// ---------------- CSR aggregation (4-way unrolled edge loop) ------------------
__global__ __launch_bounds__(256) void agg_kernel(
    const float* __restrict__ A, const float* __restrict__ B,
    const int* __restrict__ srcs, const float* __restrict__ eas,
    const int* __restrict__ off, const float* __restrict__ cvec,
    float* __restrict__ S, int N)
{
    int node = (blockIdx.x * blockDim.x + threadIdx.x) >> 5;
    if (node >= N) return;
    int lane = threadIdx.x & 31;
    const float4 a = *reinterpret_cast<const float4*>(A + (size_t)node * HID + lane * 4);
    const float4 c = *reinterpret_cast<const float4*>(cvec + lane * 4);
    float4 s = make_float4(0.f, 0.f, 0.f, 0.f);
    int p  = off[node];
    int pe = off[node + 1];
    for (; p + 3 < pe; p += 4) {
        int s0 = srcs[p], s1 = srcs[p + 1], s2 = srcs[p + 2], s3 = srcs[p + 3];
        float e0 = eas[p], e1 = eas[p + 1], e2 = eas[p + 2], e3 = eas[p + 3];
        const float4 b0 = *reinterpret_cast<const float4*>(B + (size_t)s0 * HID + lane * 4);
        const float4 b1 = *reinterpret_cast<const float4*>(B + (size_t)s1 * HID + lane * 4);
        const float4 b2 = *reinterpret_cast<const float4*>(B + (size_t)s2 * HID + lane * 4);
        const float4 b3 = *reinterpret_cast<const float4*>(B + (size_t)s3 * HID + lane * 4);
        s.x += fmaxf(fmaf(e0, c.x, a.x + b0.x), 0.0f) + fmaxf(fmaf(e1, c.x, a.x + b1.x), 0.0f)
             + fmaxf(fmaf(e2, c.x, a.x + b2.x), 0.0f) + fmaxf(fmaf(e3, c.x, a.x + b3.x), 0.0f);
        s.y += fmaxf(fmaf(e0, c.y, a.y + b0.y), 0.0f) + fmaxf(fmaf(e1, c.y, a.y + b1.y), 0.0f)
             + fmaxf(fmaf(e2, c.y, a.y + b2.y), 0.0f) + fmaxf(fmaf(e3, c.y, a.y + b3.y), 0.0f);
        s.z += fmaxf(fmaf(e0, c.z, a.z + b0.z), 0.0f) + fmaxf(fmaf(e1, c.z, a.z + b1.z), 0.0f)
             + fmaxf(fmaf(e2, c.z, a.z + b2.z), 0.0f) + fmaxf(fmaf(e3, c.z, a.z + b3.z), 0.0f);
        s.w += fmaxf(fmaf(e0, c.w, a.w + b0.w), 0.0f) + fmaxf(fmaf(e1, c.w, a.w + b1.w), 0.0f)
             + fmaxf(fmaf(e2, c.w, a.w + b2.w), 0.0f) + fmaxf(fmaf(e3, c.w, a.w + b3.w), 0.0f);
    }
    for (; p < pe; ++p) {
        int s0 = srcs[p];
        float e0 = eas[p];
        const float4 b0 = *reinterpret_cast<const float4*>(B + (size_t)s0 * HID + lane * 4);
        s.x += fmaxf(fmaf(e0, c.x, a.x + b0.x), 0.0f);
        s.y += fmaxf(fmaf(e0, c.y, a.y + b0.y), 0.0f);
        s.z += fmaxf(fmaf(e0, c.z, a.z + b0.z), 0.0f);
        s.w += fmaxf(fmaf(e0, c.w, a.w + b0.w), 0.0f);
    }
    *reinterpret_cast<float4*>(S + (size_t)node * HID + lane * 4) = s;
}

// ---------------- column sum + head ------------------------------------------
__global__ void colsum_kernel(const float* __restrict__ x, float* __restrict__ cs, int N) {
    int col = threadIdx.x & 127;
    int rg  = threadIdx.x >> 7;
    float s = 0.0f;
    for (int row = blockIdx.x * 2 + rg; row < N; row += gridDim.x * 2)
        s += x[(size_t)row * HID + col];
    atomicAdd(&cs[col], s);
}
__global__ void head_kernel(const float* __restrict__ cs,
                            const float* __restrict__ W1, const float* __restrict__ b1,
                            const float* __restrict__ W2, const float* __restrict__ b2,
                            float* __restrict__ out, float invN)
{
    __shared__ float g[HID], h[HID];
    int t = threadIdx.x;
    g[t] = cs[t] * invN;
    __syncthreads();
    float acc = b1[t];
#pragma unroll 8
    for (int k = 0; k < HID; ++k) acc = fmaf(g[k], W1[k * HID + t], acc);
    h[t] = fmaxf(acc, 0.0f);
    __syncthreads();
    float o = b2[t];
#pragma unroll 8
    for (int k = 0; k < HID; ++k) o = fmaf(h[k], W2[k * HID + t], o);
    out[t] = o;
}

// ---------------- launch ----------------------------------------------------
extern "C" void kernel_launch(void* const* d_in, const int* in_sizes, int n_in,
                              void* d_out, int out_size) {
    const float* node_feat = (const float*)d_in[0];
    const float* edge_attr = (const float*)d_in[1];
    const float* enc_W     = (const float*)d_in[2];
    const float* enc_b     = (const float*)d_in[3];
    const float* mlp_W1    = (const float*)d_in[4];
    const float* mlp_b1    = (const float*)d_in[5];
    const float* mlp_W2    = (const float*)d_in[6];
    const float* mlp_b2    = (const float*)d_in[7];
    const float* upd_W1    = (const float*)d_in[8];
    const float* upd_b1    = (const float*)d_in[9];
    const float* upd_W2    = (const float*)d_in[10];
    const float* upd_b2    = (const float*)d_in[11];
    const float* ln_g      = (const float*)d_in[12];
    const float* ln_b      = (const float*)d_in[13];
    const float* out_W1    = (const float*)d_in[14];
    const float* out_b1    = (const float*)d_in[15];
    const float* out_W2    = (const float*)d_in[16];
    const float* out_b2    = (const float*)d_in[17];
    const void*  edge_idx  = d_in[18];

    const int N = in_sizes[0] / 5;
    const int E = in_sizes[18] / 2;

    float *px, *pA, *pB, *pS, *pT, *pinv, *pmask, *pcs, *peas;
    int *pflag, *pcnt, *poff, *pcur, *pbsum, *psrcs;
    __nv_bfloat16 *pWh, *pWl;
    cudaGetSymbolAddress((void**)&px,    g_x);
    cudaGetSymbolAddress((void**)&pA,    g_A);
    cudaGetSymbolAddress((void**)&pB,    g_B);
    cudaGetSymbolAddress((void**)&pS,    g_S);
    cudaGetSymbolAddress((void**)&pT,    g_T);
    cudaGetSymbolAddress((void**)&pinv,  g_inv);
    cudaGetSymbolAddress((void**)&pmask, g_mask);
    cudaGetSymbolAddress((void**)&pcs,   g_colsum);
    cudaGetSymbolAddress((void**)&pflag, g_is64);
    cudaGetSymbolAddress((void**)&pcnt,  g_cnt);
    cudaGetSymbolAddress((void**)&poff,  g_off);
    cudaGetSymbolAddress((void**)&pcur,  g_cur);
    cudaGetSymbolAddress((void**)&pbsum, g_bsum);
    cudaGetSymbolAddress((void**)&psrcs, g_srcs);
    cudaGetSymbolAddress((void**)&peas,  g_eas);
    cudaGetSymbolAddress((void**)&pWh,   g_Wh);
    cudaGetSymbolAddress((void**)&pWl,   g_Wl);

    cudaFuncSetAttribute(mma_gemm,     cudaFuncAttributeMaxDynamicSharedMemorySize, DSMEM_SZ);
    cudaFuncSetAttribute(mma_gemm_msg, cudaFuncAttributeMaxDynamicSharedMemorySize, DSMEM_SZ);
    cudaFuncSetAttribute(update_fused, cudaFuncAttributeMaxDynamicSharedMemorySize, DSMEM_SZ);

    const int gemm_grid = (N + 127) / 128;
    const int scan_blocks = (N + 1023) / 1024;

    // --- CSR build (once; reused for all 3 layers) ---
    detect_idx_kernel<<<1, 1>>>(edge_idx, E, pflag);
    cudaMemsetAsync(pcnt, 0, (size_t)N * sizeof(int));
    hist_kernel<<<(E + 255) / 256, 256>>>(edge_idx, pflag, pcnt, E);
    scan1_kernel<<<scan_blocks, 1024>>>(pcnt, poff, pbsum, N);
    scan2_kernel<<<1, 64>>>(pbsum, scan_blocks);
    scan3_kernel<<<(N + 255) / 256, 256>>>(poff, pcur, pbsum, pcnt, pinv, pmask, N, E);
    scatter_kernel<<<(E + 255) / 256, 256>>>(edge_idx, pflag, edge_attr, pcur, psrcs, peas, E);

    encoder_kernel<<<(N * HID + 255) / 256, 256>>>(node_feat, enc_W, enc_b, px, N);
    prep_weights<<<18, 256>>>(mlp_W1, mlp_W2, upd_W1, upd_W2, pWh, pWl);

    for (int l = 0; l < 3; ++l) {
        const float* cve = mlp_W1 + (size_t)l * 257 * HID + 256 * HID; // edge_attr row
        const float* b1  = mlp_b1 + (size_t)l * HID;
        const float* b2  = mlp_b2 + (size_t)l * HID;
        const float* ub1 = upd_b1 + (size_t)l * HID;
        const float* ub2 = upd_b2 + (size_t)l * HID;
        __nv_bfloat16* W1a_h = pWh + (size_t)(l * 6 + 0) * 16384;
        __nv_bfloat16* W1a_l = pWl + (size_t)(l * 6 + 0) * 16384;
        __nv_bfloat16* W1b_h = pWh + (size_t)(l * 6 + 1) * 16384;
        __nv_bfloat16* W1b_l = pWl + (size_t)(l * 6 + 1) * 16384;
        __nv_bfloat16* W2_h  = pWh + (size_t)(l * 6 + 2) * 16384;
        __nv_bfloat16* W2_l  = pWl + (size_t)(l * 6 + 2) * 16384;
        __nv_bfloat16* U1a_h = pWh + (size_t)(l * 6 + 3) * 16384;
        __nv_bfloat16* U1a_l = pWl + (size_t)(l * 6 + 3) * 16384;
        __nv_bfloat16* U1b_h = pWh + (size_t)(l * 6 + 4) * 16384;
        __nv_bfloat16* U1b_l = pWl + (size_t)(l * 6 + 4) * 16384;
        __nv_bfloat16* U2_h  = pWh + (size_t)(l * 6 + 5) * 16384;
        __nv_bfloat16* U2_l  = pWl + (size_t)(l * 6 + 5) * 16384;

        // A_msg = x@W1a + b1 ; B_msg = x@W1b   (one fused kernel)
        mma_gemm_msg<<<gemm_grid, 256, DSMEM_SZ>>>(px, W1a_h, W1a_l, W1b_h, W1b_l,
                                                   b1, pA, pB, N);

        // S[i] = sum over CSR adj of relu(A[i]+B[src]+ea*c)
        agg_kernel<<<(N * 32 + 255) / 256, 256>>>(pA, pB, psrcs, peas, poff, cve, pS, N);

        // aggr = (S*inv_deg)@W2 + b2*[deg>0]
        mma_gemm<<<gemm_grid, 256, DSMEM_SZ>>>(pS, W2_h, W2_l, b2, pinv, pmask, pT, N);

        // x = relu(LN(relu(x@U1a + aggr@U1b + ub1)@U2 + ub2))  (one fused kernel)
        update_fused<<<gemm_grid, 256, DSMEM_SZ>>>(px, U1a_h, U1a_l, pT, U1b_h, U1b_l,
                                                   ub1, U2_h, U2_l, ub2,
                                                   ln_g + (size_t)l * HID,
                                                   ln_b + (size_t)l * HID, px, N);
    }

    cudaMemsetAsync(pcs, 0, HID * sizeof(float));
    colsum_kernel<<<128, 256>>>(px, pcs, N);
    head_kernel<<<1, HID>>>(pcs, out_W1, out_b1, out_W2, out_b2,
                            (float*)d_out, 1.0f / (float)N);
}